// round 4
// baseline (speedup 1.0000x reference)
#include <cuda_runtime.h>
#include <math.h>

// Problem constants
#define B_IMG   8
#define LTOK    4096
#define DIMC    512
#define HEADS   8
#define HD      64
#define NTOK    256           // tokens per window (16x16)
#define NWIN    128           // B * 16 windows
#define WH      (NWIN*HEADS)  // 1024
#define QSCALE  0.125f        // 64^-0.5
#define CONVK   15

// --------- device scratch (static allocations only; no cudaMalloc) ---------
__device__ float g_Q[NWIN*HEADS*NTOK*HD];      // 64 MB  (scale folded in)
__device__ float g_K[NWIN*HEADS*NTOK*HD];      // 64 MB
__device__ float g_V[NWIN*HEADS*NTOK*HD];      // 64 MB
__device__ float g_S[(size_t)WH*NTOK*NTOK];    // 256 MB raw scores
__device__ float g_bias[HEADS*NTOK*NTOK];      // 2 MB   gathered rel-pos bias
__device__ float g_O[NWIN*NTOK*DIMC];          // 64 MB  post-attention (w,n,c)

// window/token -> flat token index in (B, L) layout
__device__ __forceinline__ int win_tok_to_l(int w, int n) {
    int ww = w & 15;
    int rh = ww >> 2, rw = ww & 3;
    int i  = n >> 4,  j  = n & 15;
    return ((rh * 16 + i) << 6) + rw * 16 + j;   // (row)*64 + col
}

// --------------------------- K0: bias gather -------------------------------
// g_bias[h][n][m] = table[rel_index[n][m]][h]
__global__ void bias_kernel(const float* __restrict__ table,
                            const int*   __restrict__ rel_index) {
    int hn = blockIdx.x;            // h*256 + n
    int h  = hn >> 8, n = hn & 255;
    int m  = threadIdx.x;
    int idx = rel_index[n * NTOK + m];
    g_bias[(size_t)hn * NTOK + m] = table[idx * HEADS + h];
}

// --------------------------- K1: QKV GEMM ----------------------------------
// out[r][c] = sum_k x_gathered[r][k] * qkv_w[c][k] + qkv_b[c]
// r = (window, token) with region-partition gather; c in [0,1536)
// Epilogue scatters into g_Q (with QSCALE), g_K, g_V in (w,h,n,d) layout.
__global__ __launch_bounds__(256) void qkv_kernel(const float* __restrict__ x,
                                                  const float* __restrict__ wgt,
                                                  const float* __restrict__ bias) {
    __shared__ float As[16][68];
    __shared__ float Bs[16][68];
    int m0 = blockIdx.x * 64;
    int c0 = blockIdx.y * 64;
    int tid = threadIdx.x;
    int tx = tid & 15, ty = tid >> 4;
    int lrow = tid >> 2;              // 0..63
    int lk   = (tid & 3) << 2;        // 0,4,8,12

    int r  = m0 + lrow;
    int w  = r >> 8, n = r & 255;
    int l  = win_tok_to_l(w, n);
    const float* aptr = x   + ((size_t)((w >> 4) * LTOK + l)) * DIMC + lk;
    const float* bptr = wgt + (size_t)(c0 + lrow) * DIMC + lk;

    float acc[4][4] = {};
    for (int k0 = 0; k0 < DIMC; k0 += 16) {
        float4 av = *(const float4*)(aptr + k0);
        float4 bv = *(const float4*)(bptr + k0);
        __syncthreads();
        As[lk+0][lrow] = av.x; As[lk+1][lrow] = av.y;
        As[lk+2][lrow] = av.z; As[lk+3][lrow] = av.w;
        Bs[lk+0][lrow] = bv.x; Bs[lk+1][lrow] = bv.y;
        Bs[lk+2][lrow] = bv.z; Bs[lk+3][lrow] = bv.w;
        __syncthreads();
        #pragma unroll
        for (int k = 0; k < 16; k++) {
            float4 a4 = *(const float4*)&As[k][ty << 2];
            float4 b4 = *(const float4*)&Bs[k][tx << 2];
            float ar[4] = {a4.x, a4.y, a4.z, a4.w};
            float br[4] = {b4.x, b4.y, b4.z, b4.w};
            #pragma unroll
            for (int ri = 0; ri < 4; ri++)
                #pragma unroll
                for (int ci = 0; ci < 4; ci++)
                    acc[ri][ci] += ar[ri] * br[ci];
        }
    }
    #pragma unroll
    for (int ri = 0; ri < 4; ri++) {
        int rr = m0 + (ty << 2) + ri;
        int w2 = rr >> 8, n2 = rr & 255;
        #pragma unroll
        for (int ci = 0; ci < 4; ci++) {
            int c = c0 + (tx << 2) + ci;
            float v = acc[ri][ci] + bias[c];
            int s = c >> 9, h = (c >> 6) & 7, d = c & 63;
            size_t o = (((size_t)(w2 * HEADS + h)) * NTOK + n2) * HD + d;
            if (s == 0)      g_Q[o] = v * QSCALE;
            else if (s == 1) g_K[o] = v;
            else             g_V[o] = v;
        }
    }
}

// --------------------------- K2: scores S = q k^T --------------------------
__global__ __launch_bounds__(256) void score_kernel() {
    __shared__ float As[16][68];
    __shared__ float Bs[16][68];
    int wh = blockIdx.x;
    int n0 = blockIdx.y * 64;
    int m0 = blockIdx.z * 64;
    int tid = threadIdx.x;
    int tx = tid & 15, ty = tid >> 4;
    int lrow = tid >> 2;
    int lk   = (tid & 3) << 2;

    const float* aptr = g_Q + ((size_t)wh * NTOK + n0 + lrow) * HD + lk;
    const float* bptr = g_K + ((size_t)wh * NTOK + m0 + lrow) * HD + lk;

    float acc[4][4] = {};
    for (int k0 = 0; k0 < HD; k0 += 16) {
        float4 av = *(const float4*)(aptr + k0);
        float4 bv = *(const float4*)(bptr + k0);
        __syncthreads();
        As[lk+0][lrow] = av.x; As[lk+1][lrow] = av.y;
        As[lk+2][lrow] = av.z; As[lk+3][lrow] = av.w;
        Bs[lk+0][lrow] = bv.x; Bs[lk+1][lrow] = bv.y;
        Bs[lk+2][lrow] = bv.z; Bs[lk+3][lrow] = bv.w;
        __syncthreads();
        #pragma unroll
        for (int k = 0; k < 16; k++) {
            float4 a4 = *(const float4*)&As[k][ty << 2];
            float4 b4 = *(const float4*)&Bs[k][tx << 2];
            float ar[4] = {a4.x, a4.y, a4.z, a4.w};
            float br[4] = {b4.x, b4.y, b4.z, b4.w};
            #pragma unroll
            for (int ri = 0; ri < 4; ri++)
                #pragma unroll
                for (int ci = 0; ci < 4; ci++)
                    acc[ri][ci] += ar[ri] * br[ci];
        }
    }
    float* sout = g_S + (size_t)wh * NTOK * NTOK;
    #pragma unroll
    for (int ri = 0; ri < 4; ri++) {
        int nn = n0 + (ty << 2) + ri;
        #pragma unroll
        for (int ci = 0; ci < 4; ci++) {
            int mm = m0 + (tx << 2) + ci;
            sout[(size_t)nn * NTOK + mm] = acc[ri][ci];
        }
    }
}

// ------- K3: fused depthwise conv (15) + bias + softmax + P @ V ------------
// One block = (window*head, 32 query rows). Shared: 46-row score halo,
// 32x256 P tile, 256x64 V tile. Softmax normalization deferred to PV epilogue.
#define SMEM_F (46*256 + 32*256 + 256*64 + 32)
__global__ __launch_bounds__(256) void attn_kernel(const float* __restrict__ pew,
                                                   const float* __restrict__ peb) {
    extern __shared__ float sm[];
    float* Ssh    = sm;                   // [46][256]
    float* P      = sm + 46*256;          // [32][256]
    float* Vs     = P  + 32*256;          // [256][64]
    float* rowsum = Vs + 256*64;          // [32]

    int wh = blockIdx.x;
    int h  = wh & 7;
    int w  = wh >> 3;
    int n0 = blockIdx.y << 5;
    int tid = threadIdx.x;

    const float* Sg = g_S + (size_t)wh * NTOK * NTOK;
    for (int e = tid; e < 46 * 256; e += 256) {
        int rr = e >> 8, m = e & 255;
        int nn = n0 + rr - 7;
        Ssh[e] = (nn >= 0 && nn < NTOK) ? Sg[(size_t)nn * NTOK + m] : 0.f;
    }
    const float4* Vg  = (const float4*)(g_V + (size_t)wh * NTOK * HD);
    float4*       Vs4 = (float4*)Vs;
    for (int e = tid; e < NTOK * HD / 4; e += 256) Vs4[e] = Vg[e];

    float wpe[CONVK];
    #pragma unroll
    for (int t = 0; t < CONVK; t++) wpe[t] = pew[h * CONVK + t];
    float pbv = peb[h];
    __syncthreads();

    // conv over query axis + pe bias + relative-position bias
    {
        int m = tid;   // one column per thread
        const float* bg = g_bias + ((size_t)h * NTOK + n0) * NTOK + m;
        #pragma unroll 4
        for (int r2 = 0; r2 < 32; r2++) {
            float a = Ssh[(r2 + 7) * 256 + m] + pbv + bg[r2 * 256];
            #pragma unroll
            for (int t = 0; t < CONVK; t++)
                a += wpe[t] * Ssh[(r2 + t) * 256 + m];
            P[r2 * 256 + m] = a;
        }
    }
    __syncthreads();

    // softmax (unnormalized exp + rowsum); each warp owns 4 rows
    int lane = tid & 31, warp = tid >> 5;
    #pragma unroll
    for (int rr = 0; rr < 4; rr++) {
        int r2 = warp * 4 + rr;
        float mx = -1e30f;
        #pragma unroll
        for (int q = 0; q < 8; q++)
            mx = fmaxf(mx, P[r2 * 256 + lane + q * 32]);
        #pragma unroll
        for (int o = 16; o > 0; o >>= 1)
            mx = fmaxf(mx, __shfl_xor_sync(0xffffffffu, mx, o));
        float s = 0.f;
        #pragma unroll
        for (int q = 0; q < 8; q++) {
            float e = __expf(P[r2 * 256 + lane + q * 32] - mx);
            P[r2 * 256 + lane + q * 32] = e;
            s += e;
        }
        #pragma unroll
        for (int o = 16; o > 0; o >>= 1)
            s += __shfl_xor_sync(0xffffffffu, s, o);
        if (lane == 0) rowsum[r2] = s;
    }
    __syncthreads();

    // PV: O(32x64) = P(32x256) @ V(256x64); divide by rowsum at the end
    int tx = tid & 15, ty = tid >> 4;
    int r0 = ty * 2;
    float o0[4] = {}, o1[4] = {};
    for (int k = 0; k < 256; k++) {
        float a0 = P[r0 * 256 + k];
        float a1 = P[r0 * 256 + 256 + k];
        float4 bv = *(const float4*)&Vs[k * 64 + tx * 4];
        o0[0] += a0 * bv.x; o0[1] += a0 * bv.y; o0[2] += a0 * bv.z; o0[3] += a0 * bv.w;
        o1[0] += a1 * bv.x; o1[1] += a1 * bv.y; o1[2] += a1 * bv.z; o1[3] += a1 * bv.w;
    }
    float inv0 = 1.f / rowsum[r0];
    float inv1 = 1.f / rowsum[r0 + 1];
    float* og = g_O + (((size_t)w * NTOK) + n0 + r0) * DIMC + h * HD + tx * 4;
    float4 s0 = {o0[0]*inv0, o0[1]*inv0, o0[2]*inv0, o0[3]*inv0};
    float4 s1 = {o1[0]*inv1, o1[1]*inv1, o1[2]*inv1, o1[3]*inv1};
    *(float4*)og         = s0;
    *(float4*)(og + DIMC) = s1;
}

// --------------------------- K4: output proj + scatter ---------------------
__global__ __launch_bounds__(256) void proj_kernel(const float* __restrict__ wgt,
                                                   const float* __restrict__ bias,
                                                   float* __restrict__ out) {
    __shared__ float As[16][68];
    __shared__ float Bs[16][68];
    int m0 = blockIdx.x * 64;
    int c0 = blockIdx.y * 64;
    int tid = threadIdx.x;
    int tx = tid & 15, ty = tid >> 4;
    int lrow = tid >> 2;
    int lk   = (tid & 3) << 2;

    const float* aptr = g_O + (size_t)(m0 + lrow) * DIMC + lk;
    const float* bptr = wgt + (size_t)(c0 + lrow) * DIMC + lk;

    float acc[4][4] = {};
    for (int k0 = 0; k0 < DIMC; k0 += 16) {
        float4 av = *(const float4*)(aptr + k0);
        float4 bv = *(const float4*)(bptr + k0);
        __syncthreads();
        As[lk+0][lrow] = av.x; As[lk+1][lrow] = av.y;
        As[lk+2][lrow] = av.z; As[lk+3][lrow] = av.w;
        Bs[lk+0][lrow] = bv.x; Bs[lk+1][lrow] = bv.y;
        Bs[lk+2][lrow] = bv.z; Bs[lk+3][lrow] = bv.w;
        __syncthreads();
        #pragma unroll
        for (int k = 0; k < 16; k++) {
            float4 a4 = *(const float4*)&As[k][ty << 2];
            float4 b4 = *(const float4*)&Bs[k][tx << 2];
            float ar[4] = {a4.x, a4.y, a4.z, a4.w};
            float br[4] = {b4.x, b4.y, b4.z, b4.w};
            #pragma unroll
            for (int ri = 0; ri < 4; ri++)
                #pragma unroll
                for (int ci = 0; ci < 4; ci++)
                    acc[ri][ci] += ar[ri] * br[ci];
        }
    }
    #pragma unroll
    for (int ri = 0; ri < 4; ri++) {
        int rr = m0 + (ty << 2) + ri;
        int w2 = rr >> 8, n2 = rr & 255;
        int l  = win_tok_to_l(w2, n2);
        float* orow = out + ((size_t)((w2 >> 4) * LTOK + l)) * DIMC;
        #pragma unroll
        for (int ci = 0; ci < 4; ci++) {
            int c = c0 + (tx << 2) + ci;
            orow[c] = acc[ri][ci] + bias[c];
        }
    }
}

// ---------------------------------------------------------------------------
extern "C" void kernel_launch(void* const* d_in, const int* in_sizes, int n_in,
                              void* d_out, int out_size) {
    const float* x       = (const float*)d_in[0];
    const float* qkv_w   = (const float*)d_in[1];
    const float* qkv_b   = (const float*)d_in[2];
    const float* proj_w  = (const float*)d_in[3];
    const float* proj_b  = (const float*)d_in[4];
    const float* table   = (const float*)d_in[5];
    const float* pe_w    = (const float*)d_in[6];
    const float* pe_b    = (const float*)d_in[7];
    const int*   rel_idx = (const int*)d_in[8];
    float* out = (float*)d_out;

    cudaFuncSetAttribute(attn_kernel,
                         cudaFuncAttributeMaxDynamicSharedMemorySize,
                         SMEM_F * sizeof(float));

    bias_kernel<<<HEADS * NTOK, 256>>>(table, rel_idx);
    qkv_kernel<<<dim3(NWIN * NTOK / 64, 1536 / 64), 256>>>(x, qkv_w, qkv_b);
    score_kernel<<<dim3(WH, 4, 4), 256>>>();
    attn_kernel<<<dim3(WH, 8), 256, SMEM_F * sizeof(float)>>>(pe_w, pe_b);
    proj_kernel<<<dim3(NWIN * NTOK / 64, DIMC / 64), 256>>>(proj_w, proj_b, out);
}

// round 7
// speedup vs baseline: 2.1167x; 2.1167x over previous
#include <cuda_runtime.h>
#include <cuda_bf16.h>
#include <cstdint>
#include <math.h>

// Problem constants
#define B_IMG   8
#define LTOK    4096
#define DIMC    512
#define HEADS   8
#define HD      64
#define NTOK    256           // tokens per window (16x16)
#define NWIN    128           // B * 16 windows
#define WH      (NWIN*HEADS)  // 1024
#define QSCALE  0.125f        // 64^-0.5
#define CONVK   15

typedef __nv_bfloat16 bf16;

__device__ __forceinline__ uint32_t smem_to_u32(const void* p) {
    uint32_t a;
    asm("{ .reg .u64 t; cvta.to.shared.u64 t, %1; cvt.u32.u64 %0, t; }"
        : "=r"(a) : "l"(p));
    return a;
}

// --------- device scratch (static allocations only; no cudaMalloc) ---------
__device__ float g_Q[NWIN*HEADS*NTOK*HD];      // 64 MB  (scale folded in)
__device__ float g_K[NWIN*HEADS*NTOK*HD];      // 64 MB
__device__ float g_V[NWIN*HEADS*NTOK*HD];      // 64 MB
__device__ float g_S[(size_t)WH*NTOK*NTOK];    // 256 MB raw scores
__device__ float g_bias[HEADS*NTOK*NTOK];      // 2 MB
__device__ float g_O[NWIN*NTOK*DIMC];          // 64 MB
__device__ bf16  g_Ahb[NWIN*NTOK*DIMC];        // 32 MB  A hi (x, then O)
__device__ bf16  g_Alb[NWIN*NTOK*DIMC];        // 32 MB  A lo residual
__device__ bf16  g_Whb[3*DIMC*DIMC];           // qkv weights hi
__device__ bf16  g_Wlb[3*DIMC*DIMC];
__device__ bf16  g_PWhb[DIMC*DIMC];            // proj weights hi
__device__ bf16  g_PWlb[DIMC*DIMC];

// window/token -> flat token index in (B, L) layout
__device__ __forceinline__ int win_tok_to_l(int w, int n) {
    int ww = w & 15;
    int rh = ww >> 2, rw = ww & 3;
    int i  = n >> 4,  j  = n & 15;
    return ((rh * 16 + i) << 6) + rw * 16 + j;
}

// bf16 hi/lo split
__device__ __forceinline__ void bf_split(float v, bf16& hi, bf16& lo) {
    hi = __float2bfloat16_rn(v);
    lo = __float2bfloat16_rn(v - __bfloat162float(hi));
}

// --------------------------- K0: bias gather -------------------------------
__global__ void bias_kernel(const float* __restrict__ table,
                            const int*   __restrict__ rel_index) {
    int hn = blockIdx.x;
    int h  = hn >> 8, n = hn & 255;
    int m  = threadIdx.x;
    int idx = rel_index[n * NTOK + m];
    g_bias[(size_t)hn * NTOK + m] = table[idx * HEADS + h];
}

// ------------------- split kernels (fp32 -> bf16 hi + lo) ------------------
__global__ __launch_bounds__(128) void split_x_kernel(const float* __restrict__ x) {
    int r = blockIdx.x;                 // 0..32767 = w*256+n
    int w = r >> 8, n = r & 255;
    int l = win_tok_to_l(w, n);
    const float4* src = (const float4*)(x + ((size_t)((w >> 4) * LTOK + l)) * DIMC);
    float4 v = src[threadIdx.x];
    bf16 h4[4], l4[4];
    bf_split(v.x, h4[0], l4[0]); bf_split(v.y, h4[1], l4[1]);
    bf_split(v.z, h4[2], l4[2]); bf_split(v.w, h4[3], l4[3]);
    *(uint2*)(g_Ahb + (size_t)r * DIMC + threadIdx.x * 4) = *(uint2*)h4;
    *(uint2*)(g_Alb + (size_t)r * DIMC + threadIdx.x * 4) = *(uint2*)l4;
}

__global__ __launch_bounds__(256) void split_plain_kernel(const float* __restrict__ src,
                                                          bf16* __restrict__ hi,
                                                          bf16* __restrict__ lo) {
    size_t i = (size_t)blockIdx.x * 256 + threadIdx.x;
    float4 v = ((const float4*)src)[i];
    bf16 h4[4], l4[4];
    bf_split(v.x, h4[0], l4[0]); bf_split(v.y, h4[1], l4[1]);
    bf_split(v.z, h4[2], l4[2]); bf_split(v.w, h4[3], l4[3]);
    *(uint2*)(hi + i * 4) = *(uint2*)h4;
    *(uint2*)(lo + i * 4) = *(uint2*)l4;
}

__global__ __launch_bounds__(256) void split_o_kernel() {
    size_t i = (size_t)blockIdx.x * 256 + threadIdx.x;
    float4 v = ((const float4*)g_O)[i];
    bf16 h4[4], l4[4];
    bf_split(v.x, h4[0], l4[0]); bf_split(v.y, h4[1], l4[1]);
    bf_split(v.z, h4[2], l4[2]); bf_split(v.w, h4[3], l4[3]);
    *(uint2*)(g_Ahb + i * 4) = *(uint2*)h4;
    *(uint2*)(g_Alb + i * 4) = *(uint2*)l4;
}

// ------------- mma.sync bf16 3-pass GEMM: C = A * B^T + bias ---------------
// A: [32768 x 512] hi/lo bf16. B: [Nt x 512] hi/lo bf16. Block tile 128x128,
// 8 warps (2x4), warp tile 64x32, k-chunks of 16, double-buffered smem.
// MODE 0: epilogue scatters to g_Q (*QSCALE) / g_K / g_V.
// MODE 1: epilogue adds proj bias, region-reverse scatter to out.
#define MG_STRIDE 24                       // bf16 elems per smem row (48 B)
#define MG_TILE   (128*MG_STRIDE)          // one matrix: 3072 elems = 6144 B
#define MG_STAGE  (4*MG_TILE)              // Ah|Al|Bh|Bl = 24576 B
#define MG_SMEM   (2*MG_STAGE*2)           // bytes: 49152

__device__ __forceinline__ void ldsm_x4(uint32_t* r, uint32_t addr) {
    asm volatile("ldmatrix.sync.aligned.m8n8.x4.shared.b16 {%0,%1,%2,%3}, [%4];"
                 : "=r"(r[0]), "=r"(r[1]), "=r"(r[2]), "=r"(r[3]) : "r"(addr));
}
__device__ __forceinline__ void ldsm_x2(uint32_t* r, uint32_t addr) {
    asm volatile("ldmatrix.sync.aligned.m8n8.x2.shared.b16 {%0,%1}, [%2];"
                 : "=r"(r[0]), "=r"(r[1]) : "r"(addr));
}
__device__ __forceinline__ void mma_bf16(float* c, const uint32_t* a, const uint32_t* b) {
    asm volatile(
        "mma.sync.aligned.m16n8k16.row.col.f32.bf16.bf16.f32 "
        "{%0,%1,%2,%3}, {%4,%5,%6,%7}, {%8,%9}, {%0,%1,%2,%3};"
        : "+f"(c[0]), "+f"(c[1]), "+f"(c[2]), "+f"(c[3])
        : "r"(a[0]), "r"(a[1]), "r"(a[2]), "r"(a[3]), "r"(b[0]), "r"(b[1]));
}

template <int MODE>
__global__ __launch_bounds__(256, 1)
void mgemm_kernel(const bf16* __restrict__ Bh_g, const bf16* __restrict__ Bl_g,
                  const float* __restrict__ bias, float* __restrict__ outp) {
    extern __shared__ bf16 smem[];
    int tid  = threadIdx.x;
    int lane = tid & 31, warp = tid >> 5;
    int wm = warp & 1, wn = warp >> 1;
    int m0 = blockIdx.x * 128;
    int n0 = blockIdx.y * 128;

    const bf16* Ah_g = g_Ahb;
    const bf16* Al_g = g_Alb;

    int ldrow = tid >> 1;            // 0..127
    int ldk   = (tid & 1) * 8;       // 0 or 8

    const bf16* gA_h = Ah_g + (size_t)(m0 + ldrow) * DIMC + ldk;
    const bf16* gA_l = Al_g + (size_t)(m0 + ldrow) * DIMC + ldk;
    const bf16* gB_h = Bh_g + (size_t)(n0 + ldrow) * DIMC + ldk;
    const bf16* gB_l = Bl_g + (size_t)(n0 + ldrow) * DIMC + ldk;
    bf16* sdst = smem + ldrow * MG_STRIDE + ldk;   // + stage/matrix offsets

    float acc[4][4][4] = {};

    // stage 0 load
    {
        *(uint4*)(sdst)             = *(const uint4*)(gA_h);
        *(uint4*)(sdst + MG_TILE)   = *(const uint4*)(gA_l);
        *(uint4*)(sdst + 2*MG_TILE) = *(const uint4*)(gB_h);
        *(uint4*)(sdst + 3*MG_TILE) = *(const uint4*)(gB_l);
    }
    __syncthreads();

    uint32_t sbase = smem_to_u32(smem);
    // fragment smem addresses (bytes)
    uint32_t aoff = (uint32_t)(((wm * 64 + (lane & 15)) * MG_STRIDE + (lane >> 4) * 8) * 2);
    uint32_t boff = (uint32_t)(((wn * 32 + (lane & 7)) * MG_STRIDE + ((lane >> 3) & 1) * 8) * 2);

    const int NC = DIMC / 16;   // 32
    for (int c = 0; c < NC; c++) {
        int buf = c & 1;
        uint4 pA, pAl, pB, pBl;
        if (c + 1 < NC) {
            int k0 = (c + 1) * 16;
            pA  = *(const uint4*)(gA_h + k0);
            pAl = *(const uint4*)(gA_l + k0);
            pB  = *(const uint4*)(gB_h + k0);
            pBl = *(const uint4*)(gB_l + k0);
        }

        uint32_t st = sbase + buf * (MG_STAGE * 2);
        uint32_t ah[4][4], al[4][4], bh[4][2], bl[4][2];
        #pragma unroll
        for (int mi = 0; mi < 4; mi++) {
            uint32_t ad = st + aoff + (uint32_t)(mi * 16 * MG_STRIDE * 2);
            ldsm_x4(ah[mi], ad);
            ldsm_x4(al[mi], ad + MG_TILE * 2);
        }
        #pragma unroll
        for (int ni = 0; ni < 4; ni++) {
            uint32_t bd = st + boff + (uint32_t)((2 * MG_TILE + ni * 8 * MG_STRIDE) * 2);
            ldsm_x2(bh[ni], bd);
            ldsm_x2(bl[ni], bd + MG_TILE * 2);
        }
        #pragma unroll
        for (int mi = 0; mi < 4; mi++)
            #pragma unroll
            for (int ni = 0; ni < 4; ni++) {
                mma_bf16(acc[mi][ni], ah[mi], bh[ni]);
                mma_bf16(acc[mi][ni], ah[mi], bl[ni]);
                mma_bf16(acc[mi][ni], al[mi], bh[ni]);
            }

        if (c + 1 < NC) {
            __syncthreads();
            bf16* d2 = sdst + (buf ^ 1) * (MG_STAGE);
            *(uint4*)(d2)             = pA;
            *(uint4*)(d2 + MG_TILE)   = pAl;
            *(uint4*)(d2 + 2*MG_TILE) = pB;
            *(uint4*)(d2 + 3*MG_TILE) = pBl;
            __syncthreads();
        }
    }

    // epilogue
    #pragma unroll
    for (int mi = 0; mi < 4; mi++) {
        int r0 = m0 + wm * 64 + mi * 16 + (lane >> 2);
        #pragma unroll
        for (int ni = 0; ni < 4; ni++) {
            int cb = n0 + wn * 32 + ni * 8 + (lane & 3) * 2;
            float b0 = bias[cb], b1 = bias[cb + 1];
            #pragma unroll
            for (int half = 0; half < 2; half++) {
                int r = r0 + half * 8;
                float v0 = acc[mi][ni][half * 2 + 0] + b0;
                float v1 = acc[mi][ni][half * 2 + 1] + b1;
                int w2 = r >> 8, n2 = r & 255;
                if (MODE == 0) {
                    int s = cb >> 9, h = (cb >> 6) & 7, d = cb & 63;
                    float scl = (s == 0) ? QSCALE : 1.0f;
                    float* dst = (s == 0 ? g_Q : (s == 1 ? g_K : g_V)) +
                                 (((size_t)(w2 * HEADS + h)) * NTOK + n2) * HD + d;
                    float2 v = {v0 * scl, v1 * scl};
                    *(float2*)dst = v;
                } else {
                    int l = win_tok_to_l(w2, n2);
                    float* dst = outp + ((size_t)((w2 >> 4) * LTOK + l)) * DIMC + cb;
                    float2 v = {v0, v1};
                    *(float2*)dst = v;
                }
            }
        }
    }
}

// --------------------------- K2: scores S = q k^T (fp32) -------------------
__global__ __launch_bounds__(256) void score_kernel() {
    __shared__ float As[16][68];
    __shared__ float Bs[16][68];
    int wh = blockIdx.x;
    int n0 = blockIdx.y * 64;
    int m0 = blockIdx.z * 64;
    int tid = threadIdx.x;
    int tx = tid & 15, ty = tid >> 4;
    int lrow = tid >> 2;
    int lk   = (tid & 3) << 2;

    const float* aptr = g_Q + ((size_t)wh * NTOK + n0 + lrow) * HD + lk;
    const float* bptr = g_K + ((size_t)wh * NTOK + m0 + lrow) * HD + lk;

    float acc[4][4] = {};
    for (int k0 = 0; k0 < HD; k0 += 16) {
        float4 av = *(const float4*)(aptr + k0);
        float4 bv = *(const float4*)(bptr + k0);
        __syncthreads();
        As[lk+0][lrow] = av.x; As[lk+1][lrow] = av.y;
        As[lk+2][lrow] = av.z; As[lk+3][lrow] = av.w;
        Bs[lk+0][lrow] = bv.x; Bs[lk+1][lrow] = bv.y;
        Bs[lk+2][lrow] = bv.z; Bs[lk+3][lrow] = bv.w;
        __syncthreads();
        #pragma unroll
        for (int k = 0; k < 16; k++) {
            float4 a4 = *(const float4*)&As[k][ty << 2];
            float4 b4 = *(const float4*)&Bs[k][tx << 2];
            float ar[4] = {a4.x, a4.y, a4.z, a4.w};
            float br[4] = {b4.x, b4.y, b4.z, b4.w};
            #pragma unroll
            for (int ri = 0; ri < 4; ri++)
                #pragma unroll
                for (int ci = 0; ci < 4; ci++)
                    acc[ri][ci] += ar[ri] * br[ci];
        }
    }
    float* sout = g_S + (size_t)wh * NTOK * NTOK;
    #pragma unroll
    for (int ri = 0; ri < 4; ri++) {
        int nn = n0 + (ty << 2) + ri;
        #pragma unroll
        for (int ci = 0; ci < 4; ci++) {
            int mm = m0 + (tx << 2) + ci;
            sout[(size_t)nn * NTOK + mm] = acc[ri][ci];
        }
    }
}

// ------- K3: fused conv + bias + softmax + P @ V (fp32) --------------------
#define SMEM_F (46*256 + 32*256 + 256*64 + 32)
__global__ __launch_bounds__(256) void attn_kernel(const float* __restrict__ pew,
                                                   const float* __restrict__ peb) {
    extern __shared__ float smf[];
    float* Ssh    = smf;                  // [46][256]
    float* P      = smf + 46*256;         // [32][256]
    float* Vs     = P  + 32*256;          // [256][64]
    float* rowsum = Vs + 256*64;          // [32]

    int wh = blockIdx.x;
    int h  = wh & 7;
    int w  = wh >> 3;
    int n0 = blockIdx.y << 5;
    int tid = threadIdx.x;

    const float* Sg = g_S + (size_t)wh * NTOK * NTOK;
    for (int e = tid; e < 46 * 256; e += 256) {
        int rr = e >> 8, m = e & 255;
        int nn = n0 + rr - 7;
        Ssh[e] = (nn >= 0 && nn < NTOK) ? Sg[(size_t)nn * NTOK + m] : 0.f;
    }
    const float4* Vg  = (const float4*)(g_V + (size_t)wh * NTOK * HD);
    float4*       Vs4 = (float4*)Vs;
    for (int e = tid; e < NTOK * HD / 4; e += 256) Vs4[e] = Vg[e];

    float wpe[CONVK];
    #pragma unroll
    for (int t = 0; t < CONVK; t++) wpe[t] = pew[h * CONVK + t];
    float pbv = peb[h];
    __syncthreads();

    {
        int m = tid;
        const float* bg = g_bias + ((size_t)h * NTOK + n0) * NTOK + m;
        #pragma unroll 4
        for (int r2 = 0; r2 < 32; r2++) {
            float a = Ssh[(r2 + 7) * 256 + m] + pbv + bg[r2 * 256];
            #pragma unroll
            for (int t = 0; t < CONVK; t++)
                a += wpe[t] * Ssh[(r2 + t) * 256 + m];
            P[r2 * 256 + m] = a;
        }
    }
    __syncthreads();

    int lane = tid & 31, warp = tid >> 5;
    #pragma unroll
    for (int rr = 0; rr < 4; rr++) {
        int r2 = warp * 4 + rr;
        float mx = -1e30f;
        #pragma unroll
        for (int q = 0; q < 8; q++)
            mx = fmaxf(mx, P[r2 * 256 + lane + q * 32]);
        #pragma unroll
        for (int o = 16; o > 0; o >>= 1)
            mx = fmaxf(mx, __shfl_xor_sync(0xffffffffu, mx, o));
        float s = 0.f;
        #pragma unroll
        for (int q = 0; q < 8; q++) {
            float e = __expf(P[r2 * 256 + lane + q * 32] - mx);
            P[r2 * 256 + lane + q * 32] = e;
            s += e;
        }
        #pragma unroll
        for (int o = 16; o > 0; o >>= 1)
            s += __shfl_xor_sync(0xffffffffu, s, o);
        if (lane == 0) rowsum[r2] = s;
    }
    __syncthreads();

    int tx = tid & 15, ty = tid >> 4;
    int r0 = ty * 2;
    float o0[4] = {}, o1[4] = {};
    for (int k = 0; k < 256; k++) {
        float a0 = P[r0 * 256 + k];
        float a1 = P[r0 * 256 + 256 + k];
        float4 bv = *(const float4*)&Vs[k * 64 + tx * 4];
        o0[0] += a0 * bv.x; o0[1] += a0 * bv.y; o0[2] += a0 * bv.z; o0[3] += a0 * bv.w;
        o1[0] += a1 * bv.x; o1[1] += a1 * bv.y; o1[2] += a1 * bv.z; o1[3] += a1 * bv.w;
    }
    float inv0 = 1.f / rowsum[r0];
    float inv1 = 1.f / rowsum[r0 + 1];
    float* og = g_O + (((size_t)w * NTOK) + n0 + r0) * DIMC + h * HD + tx * 4;
    float4 s0 = {o0[0]*inv0, o0[1]*inv0, o0[2]*inv0, o0[3]*inv0};
    float4 s1 = {o1[0]*inv1, o1[1]*inv1, o1[2]*inv1, o1[3]*inv1};
    *(float4*)og          = s0;
    *(float4*)(og + DIMC) = s1;
}

// ---------------------------------------------------------------------------
extern "C" void kernel_launch(void* const* d_in, const int* in_sizes, int n_in,
                              void* d_out, int out_size) {
    const float* x       = (const float*)d_in[0];
    const float* qkv_w   = (const float*)d_in[1];
    const float* qkv_b   = (const float*)d_in[2];
    const float* proj_w  = (const float*)d_in[3];
    const float* proj_b  = (const float*)d_in[4];
    const float* table   = (const float*)d_in[5];
    const float* pe_w    = (const float*)d_in[6];
    const float* pe_b    = (const float*)d_in[7];
    const int*   rel_idx = (const int*)d_in[8];
    float* out = (float*)d_out;

    cudaFuncSetAttribute(attn_kernel,
                         cudaFuncAttributeMaxDynamicSharedMemorySize,
                         SMEM_F * sizeof(float));
    cudaFuncSetAttribute(mgemm_kernel<0>,
                         cudaFuncAttributeMaxDynamicSharedMemorySize, MG_SMEM);
    cudaFuncSetAttribute(mgemm_kernel<1>,
                         cudaFuncAttributeMaxDynamicSharedMemorySize, MG_SMEM);

    bf16 *Wh, *Wl, *PWh, *PWl;
    cudaGetSymbolAddress((void**)&Wh,  g_Whb);
    cudaGetSymbolAddress((void**)&Wl,  g_Wlb);
    cudaGetSymbolAddress((void**)&PWh, g_PWhb);
    cudaGetSymbolAddress((void**)&PWl, g_PWlb);

    bias_kernel<<<HEADS * NTOK, 256>>>(table, rel_idx);
    split_x_kernel<<<NWIN * NTOK, 128>>>(x);
    split_plain_kernel<<<(3 * DIMC * DIMC) / 1024, 256>>>(qkv_w, Wh, Wl);
    split_plain_kernel<<<(DIMC * DIMC) / 1024, 256>>>(proj_w, PWh, PWl);

    mgemm_kernel<0><<<dim3(256, 12), 256, MG_SMEM>>>(Wh, Wl, qkv_b, nullptr);
    score_kernel<<<dim3(WH, 4, 4), 256>>>();
    attn_kernel<<<dim3(WH, 8), 256, SMEM_F * sizeof(float)>>>(pe_w, pe_b);
    split_o_kernel<<<(NWIN * NTOK * DIMC) / 1024, 256>>>();
    mgemm_kernel<1><<<dim3(256, 4), 256, MG_SMEM>>>(PWh, PWl, proj_b, out);
}

// round 8
// speedup vs baseline: 3.9757x; 1.8782x over previous
#include <cuda_runtime.h>
#include <cuda_bf16.h>
#include <cstdint>
#include <math.h>

// Problem constants
#define B_IMG   8
#define LTOK    4096
#define DIMC    512
#define HEADS   8
#define HD      64
#define NTOK    256           // tokens per window (16x16)
#define NWIN    128           // B * 16 windows
#define WH      (NWIN*HEADS)  // 1024
#define QSCALE  0.125f        // 64^-0.5
#define CONVK   15

typedef __nv_bfloat16 bf16;

__device__ __forceinline__ uint32_t smem_to_u32(const void* p) {
    uint32_t a;
    asm("{ .reg .u64 t; cvta.to.shared.u64 t, %1; cvt.u32.u64 %0, t; }"
        : "=r"(a) : "l"(p));
    return a;
}

// --------- device scratch (static allocations only; no cudaMalloc) ---------
__device__ float g_bias[HEADS*NTOK*NTOK];      // 2 MB   gathered rel-pos bias
__device__ bf16  g_Ahb[NWIN*NTOK*DIMC];        // 32 MB  A hi (x, then O)
__device__ bf16  g_Alb[NWIN*NTOK*DIMC];        // 32 MB  A lo residual
__device__ bf16  g_Whb[3*DIMC*DIMC];           // qkv weights hi
__device__ bf16  g_Wlb[3*DIMC*DIMC];
__device__ bf16  g_PWhb[DIMC*DIMC];            // proj weights hi
__device__ bf16  g_PWlb[DIMC*DIMC];
__device__ bf16  g_Qh[WH*NTOK*HD];             // 16 MB each: Q/K/V hi+lo
__device__ bf16  g_Ql[WH*NTOK*HD];
__device__ bf16  g_Kh[WH*NTOK*HD];
__device__ bf16  g_Kl[WH*NTOK*HD];
__device__ bf16  g_Vh[WH*NTOK*HD];
__device__ bf16  g_Vl[WH*NTOK*HD];

// window/token -> flat token index in (B, L) layout
__device__ __forceinline__ int win_tok_to_l(int w, int n) {
    int ww = w & 15;
    int rh = ww >> 2, rw = ww & 3;
    int i  = n >> 4,  j  = n & 15;
    return ((rh * 16 + i) << 6) + rw * 16 + j;
}

// bf16 hi/lo split
__device__ __forceinline__ void bf_split(float v, bf16& hi, bf16& lo) {
    hi = __float2bfloat16_rn(v);
    lo = __float2bfloat16_rn(v - __bfloat162float(hi));
}
__device__ __forceinline__ uint32_t bpack(bf16 a, bf16 b) {
    uint16_t xa = *(uint16_t*)&a, xb = *(uint16_t*)&b;
    return (uint32_t)xa | ((uint32_t)xb << 16);
}

// --------------------------- K0: bias gather -------------------------------
__global__ void bias_kernel(const float* __restrict__ table,
                            const int*   __restrict__ rel_index) {
    int hn = blockIdx.x;
    int hh = hn >> 8, n = hn & 255;
    int m  = threadIdx.x;
    int idx = rel_index[n * NTOK + m];
    g_bias[(size_t)hn * NTOK + m] = table[idx * HEADS + hh];
}

// ------------------- split kernels (fp32 -> bf16 hi + lo) ------------------
__global__ __launch_bounds__(128) void split_x_kernel(const float* __restrict__ x) {
    int r = blockIdx.x;                 // 0..32767 = w*256+n
    int w = r >> 8, n = r & 255;
    int l = win_tok_to_l(w, n);
    const float4* src = (const float4*)(x + ((size_t)((w >> 4) * LTOK + l)) * DIMC);
    float4 v = src[threadIdx.x];
    bf16 h4[4], l4[4];
    bf_split(v.x, h4[0], l4[0]); bf_split(v.y, h4[1], l4[1]);
    bf_split(v.z, h4[2], l4[2]); bf_split(v.w, h4[3], l4[3]);
    *(uint2*)(g_Ahb + (size_t)r * DIMC + threadIdx.x * 4) = *(uint2*)h4;
    *(uint2*)(g_Alb + (size_t)r * DIMC + threadIdx.x * 4) = *(uint2*)l4;
}

__global__ __launch_bounds__(256) void split_plain_kernel(const float* __restrict__ src,
                                                          bf16* __restrict__ hi,
                                                          bf16* __restrict__ lo) {
    size_t i = (size_t)blockIdx.x * 256 + threadIdx.x;
    float4 v = ((const float4*)src)[i];
    bf16 h4[4], l4[4];
    bf_split(v.x, h4[0], l4[0]); bf_split(v.y, h4[1], l4[1]);
    bf_split(v.z, h4[2], l4[2]); bf_split(v.w, h4[3], l4[3]);
    *(uint2*)(hi + i * 4) = *(uint2*)h4;
    *(uint2*)(lo + i * 4) = *(uint2*)l4;
}

// --------------------------- mma primitives --------------------------------
__device__ __forceinline__ void ldsm_x4(uint32_t* r, uint32_t addr) {
    asm volatile("ldmatrix.sync.aligned.m8n8.x4.shared.b16 {%0,%1,%2,%3}, [%4];"
                 : "=r"(r[0]), "=r"(r[1]), "=r"(r[2]), "=r"(r[3]) : "r"(addr));
}
__device__ __forceinline__ void ldsm_x2(uint32_t* r, uint32_t addr) {
    asm volatile("ldmatrix.sync.aligned.m8n8.x2.shared.b16 {%0,%1}, [%2];"
                 : "=r"(r[0]), "=r"(r[1]) : "r"(addr));
}
__device__ __forceinline__ void ldsm_x2_trans(uint32_t* r, uint32_t addr) {
    asm volatile("ldmatrix.sync.aligned.m8n8.x2.trans.shared.b16 {%0,%1}, [%2];"
                 : "=r"(r[0]), "=r"(r[1]) : "r"(addr));
}
__device__ __forceinline__ void mma_bf16(float* c, const uint32_t* a, const uint32_t* b) {
    asm volatile(
        "mma.sync.aligned.m16n8k16.row.col.f32.bf16.bf16.f32 "
        "{%0,%1,%2,%3}, {%4,%5,%6,%7}, {%8,%9}, {%0,%1,%2,%3};"
        : "+f"(c[0]), "+f"(c[1]), "+f"(c[2]), "+f"(c[3])
        : "r"(a[0]), "r"(a[1]), "r"(a[2]), "r"(a[3]), "r"(b[0]), "r"(b[1]));
}

// ------------- mma.sync bf16 3-pass GEMM: C = A * B^T + bias ---------------
#define MG_STRIDE 24                       // bf16 elems per smem row (48 B)
#define MG_TILE   (128*MG_STRIDE)
#define MG_STAGE  (4*MG_TILE)
#define MG_SMEM   (2*MG_STAGE*2)

template <int MODE>
__global__ __launch_bounds__(256, 1)
void mgemm_kernel(const bf16* __restrict__ Bh_g, const bf16* __restrict__ Bl_g,
                  const float* __restrict__ bias, float* __restrict__ outp) {
    extern __shared__ bf16 smem[];
    int tid  = threadIdx.x;
    int lane = tid & 31, warp = tid >> 5;
    int wm = warp & 1, wn = warp >> 1;
    int m0 = blockIdx.x * 128;
    int n0 = blockIdx.y * 128;

    int ldrow = tid >> 1;
    int ldk   = (tid & 1) * 8;

    const bf16* gA_h = g_Ahb + (size_t)(m0 + ldrow) * DIMC + ldk;
    const bf16* gA_l = g_Alb + (size_t)(m0 + ldrow) * DIMC + ldk;
    const bf16* gB_h = Bh_g + (size_t)(n0 + ldrow) * DIMC + ldk;
    const bf16* gB_l = Bl_g + (size_t)(n0 + ldrow) * DIMC + ldk;
    bf16* sdst = smem + ldrow * MG_STRIDE + ldk;

    float acc[4][4][4] = {};

    *(uint4*)(sdst)             = *(const uint4*)(gA_h);
    *(uint4*)(sdst + MG_TILE)   = *(const uint4*)(gA_l);
    *(uint4*)(sdst + 2*MG_TILE) = *(const uint4*)(gB_h);
    *(uint4*)(sdst + 3*MG_TILE) = *(const uint4*)(gB_l);
    __syncthreads();

    uint32_t sbase = smem_to_u32(smem);
    uint32_t aoff = (uint32_t)(((wm * 64 + (lane & 15)) * MG_STRIDE + (lane >> 4) * 8) * 2);
    uint32_t boff = (uint32_t)(((wn * 32 + (lane & 7)) * MG_STRIDE + ((lane >> 3) & 1) * 8) * 2);

    const int NC = DIMC / 16;
    for (int c = 0; c < NC; c++) {
        int buf = c & 1;
        uint4 pA, pAl, pB, pBl;
        if (c + 1 < NC) {
            int k0 = (c + 1) * 16;
            pA  = *(const uint4*)(gA_h + k0);
            pAl = *(const uint4*)(gA_l + k0);
            pB  = *(const uint4*)(gB_h + k0);
            pBl = *(const uint4*)(gB_l + k0);
        }
        uint32_t st = sbase + buf * (MG_STAGE * 2);
        uint32_t ah[4][4], al[4][4], bh[4][2], bl[4][2];
        #pragma unroll
        for (int mi = 0; mi < 4; mi++) {
            uint32_t ad = st + aoff + (uint32_t)(mi * 16 * MG_STRIDE * 2);
            ldsm_x4(ah[mi], ad);
            ldsm_x4(al[mi], ad + MG_TILE * 2);
        }
        #pragma unroll
        for (int ni = 0; ni < 4; ni++) {
            uint32_t bd = st + boff + (uint32_t)((2 * MG_TILE + ni * 8 * MG_STRIDE) * 2);
            ldsm_x2(bh[ni], bd);
            ldsm_x2(bl[ni], bd + MG_TILE * 2);
        }
        #pragma unroll
        for (int mi = 0; mi < 4; mi++)
            #pragma unroll
            for (int ni = 0; ni < 4; ni++) {
                mma_bf16(acc[mi][ni], ah[mi], bh[ni]);
                mma_bf16(acc[mi][ni], ah[mi], bl[ni]);
                mma_bf16(acc[mi][ni], al[mi], bh[ni]);
            }
        if (c + 1 < NC) {
            __syncthreads();
            bf16* d2 = sdst + (buf ^ 1) * (MG_STAGE);
            *(uint4*)(d2)             = pA;
            *(uint4*)(d2 + MG_TILE)   = pAl;
            *(uint4*)(d2 + 2*MG_TILE) = pB;
            *(uint4*)(d2 + 3*MG_TILE) = pBl;
            __syncthreads();
        }
    }

    #pragma unroll
    for (int mi = 0; mi < 4; mi++) {
        int r0 = m0 + wm * 64 + mi * 16 + (lane >> 2);
        #pragma unroll
        for (int ni = 0; ni < 4; ni++) {
            int cb = n0 + wn * 32 + ni * 8 + (lane & 3) * 2;
            float b0 = bias[cb], b1 = bias[cb + 1];
            #pragma unroll
            for (int half = 0; half < 2; half++) {
                int r = r0 + half * 8;
                float v0 = acc[mi][ni][half * 2 + 0] + b0;
                float v1 = acc[mi][ni][half * 2 + 1] + b1;
                int w2 = r >> 8, n2 = r & 255;
                if (MODE == 0) {
                    int s = cb >> 9, hh = (cb >> 6) & 7, d = cb & 63;
                    float scl = (s == 0) ? QSCALE : 1.0f;
                    size_t o = (((size_t)(w2 * HEADS + hh)) * NTOK + n2) * HD + d;
                    bf16* dh = (s == 0 ? g_Qh : (s == 1 ? g_Kh : g_Vh)) + o;
                    bf16* dl = (s == 0 ? g_Ql : (s == 1 ? g_Kl : g_Vl)) + o;
                    bf16 h0, l0, h1, l1;
                    bf_split(v0 * scl, h0, l0);
                    bf_split(v1 * scl, h1, l1);
                    *(uint32_t*)dh = bpack(h0, h1);
                    *(uint32_t*)dl = bpack(l0, l1);
                } else {
                    int l = win_tok_to_l(w2, n2);
                    float* dst = outp + ((size_t)((w2 >> 4) * LTOK + l)) * DIMC + cb;
                    float2 v = {v0, v1};
                    *(float2*)dst = v;
                }
            }
        }
    }
}

// ========== fused attention: S=QK^T -> conv -> softmax -> PV (all mma) =====
// one block = (window*head, 64-query tile). S halo 96 rows (mma-aligned).
// smem byte offsets (total 231680, overlaid by phase):
#define FA_S    0        // fp32 [96][256]  98304   (phase 1-2; then Vh/Vl)
#define FA_QH   98304    // bf16 [96][72]   13824
#define FA_QL   112128
#define FA_KH   125952   // bf16 [256][72]  36864
#define FA_KL   162816   //                 (ends 199680)
#define FA_C    98304    // fp32 [64][256]  65536   (phase 3-4, over Q/K)
#define FA_VH   0        // bf16 [256][72]  36864   (phase 4+, over S)
#define FA_VL   36864
#define FA_PH   163840   // bf16 [64][264]  33792
#define FA_PL   197632   //                 (ends 231424)
#define FA_RS   231424   // fp32 [64]
#define FA_SMEM 231680

__global__ __launch_bounds__(256, 1)
void fattn_kernel(const float* __restrict__ pew, const float* __restrict__ peb) {
    extern __shared__ char fsm[];
    float* S  = (float*)(fsm + FA_S);
    bf16* sQh = (bf16*)(fsm + FA_QH);
    bf16* sQl = (bf16*)(fsm + FA_QL);
    bf16* sKh = (bf16*)(fsm + FA_KH);
    bf16* sKl = (bf16*)(fsm + FA_KL);
    float* C  = (float*)(fsm + FA_C);
    bf16* sVh = (bf16*)(fsm + FA_VH);
    bf16* sVl = (bf16*)(fsm + FA_VL);
    bf16* sPh = (bf16*)(fsm + FA_PH);
    bf16* sPl = (bf16*)(fsm + FA_PL);
    float* rowsum = (float*)(fsm + FA_RS);

    int wh = blockIdx.x;
    int n0 = blockIdx.y * 64;
    int hh = wh & 7, w = wh >> 3;
    int tid = threadIdx.x, lane = tid & 31, warp = tid >> 5;
    uint32_t sbase = smem_to_u32(fsm);

    const bf16* gQh = g_Qh + (size_t)wh * NTOK * HD;
    const bf16* gQl = g_Ql + (size_t)wh * NTOK * HD;
    const bf16* gKh = g_Kh + (size_t)wh * NTOK * HD;
    const bf16* gKl = g_Kl + (size_t)wh * NTOK * HD;
    const bf16* gVh = g_Vh + (size_t)wh * NTOK * HD;
    const bf16* gVl = g_Vl + (size_t)wh * NTOK * HD;

    // ---- phase 1: load Q halo (96 rows, zero out-of-window) + K (256 rows)
    #pragma unroll
    for (int i = 0; i < 3; i++) {
        int idx = tid + i * 256;
        int r = idx >> 3, ch = idx & 7;
        int n = n0 + r - 16;
        uint4 vh = make_uint4(0, 0, 0, 0), vl = make_uint4(0, 0, 0, 0);
        if (n >= 0 && n < NTOK) {
            vh = *(const uint4*)(gQh + n * HD + ch * 8);
            vl = *(const uint4*)(gQl + n * HD + ch * 8);
        }
        *(uint4*)(sQh + r * 72 + ch * 8) = vh;
        *(uint4*)(sQl + r * 72 + ch * 8) = vl;
    }
    #pragma unroll
    for (int i = 0; i < 8; i++) {
        int idx = tid + i * 256;
        int r = idx >> 3, ch = idx & 7;
        *(uint4*)(sKh + r * 72 + ch * 8) = *(const uint4*)(gKh + r * HD + ch * 8);
        *(uint4*)(sKl + r * 72 + ch * 8) = *(const uint4*)(gKl + r * HD + ch * 8);
    }
    __syncthreads();

    // ---- phase 2: S[96][256] = Q K^T, 3-pass mma, XOR-swizzled fp32 store
    {
        int wm = warp & 1, wn = warp >> 1;            // 2 x 4 warps, tile 48x64
        float acc[3][8][4] = {};
        uint32_t ao = (uint32_t)(((wm * 48 + (lane & 15)) * 72 + (lane >> 4) * 8) * 2);
        uint32_t bo = (uint32_t)(((wn * 64 + (lane & 7)) * 72 + ((lane >> 3) & 1) * 8) * 2);
        #pragma unroll
        for (int c = 0; c < 4; c++) {
            uint32_t ah[3][4], al[3][4], bh[8][2], bl[8][2];
            #pragma unroll
            for (int mi = 0; mi < 3; mi++) {
                uint32_t ad = sbase + FA_QH + ao + (uint32_t)((mi * 16 * 72 + c * 16) * 2);
                ldsm_x4(ah[mi], ad);
                ldsm_x4(al[mi], ad + (FA_QL - FA_QH));
            }
            #pragma unroll
            for (int ni = 0; ni < 8; ni++) {
                uint32_t bd = sbase + FA_KH + bo + (uint32_t)((ni * 8 * 72 + c * 16) * 2);
                ldsm_x2(bh[ni], bd);
                ldsm_x2(bl[ni], bd + (FA_KL - FA_KH));
            }
            #pragma unroll
            for (int mi = 0; mi < 3; mi++)
                #pragma unroll
                for (int ni = 0; ni < 8; ni++) {
                    mma_bf16(acc[mi][ni], ah[mi], bh[ni]);
                    mma_bf16(acc[mi][ni], ah[mi], bl[ni]);
                    mma_bf16(acc[mi][ni], al[mi], bh[ni]);
                }
        }
        #pragma unroll
        for (int mi = 0; mi < 3; mi++) {
            int r = wm * 48 + mi * 16 + (lane >> 2);
            #pragma unroll
            for (int ni = 0; ni < 8; ni++) {
                int colb = wn * 64 + ni * 8 + (lane & 3) * 2;
                int c0 = colb ^ ((r & 7) << 2);
                float2 v0 = {acc[mi][ni][0], acc[mi][ni][1]};
                *(float2*)&S[r * 256 + c0] = v0;
                int r8 = r + 8;
                int c1 = colb ^ ((r8 & 7) << 2);
                float2 v1 = {acc[mi][ni][2], acc[mi][ni][3]};
                *(float2*)&S[r8 * 256 + c1] = v1;
            }
        }
    }
    __syncthreads();

    // ---- phase 3: 15-tap conv over query axis + pe bias + rel-pos bias
    {
        float wpe[CONVK];
        #pragma unroll
        for (int t = 0; t < CONVK; t++) wpe[t] = pew[hh * CONVK + t];
        float pbv = peb[hh];
        int m = tid;
        const float* bg = g_bias + ((size_t)hh * NTOK + n0) * NTOK + m;
        float buf[CONVK];                 // ring: row x at slot (x-9)%15
        #pragma unroll
        for (int t = 0; t < CONVK; t++) {
            int row = 9 + t;
            buf[t] = S[row * 256 + (m ^ ((row & 7) << 2))];
        }
        #pragma unroll
        for (int r2 = 0; r2 < 64; r2++) {
            float a = buf[(r2 + 7) % CONVK] + pbv + bg[r2 * 256];
            #pragma unroll
            for (int t = 0; t < CONVK; t++)
                a += wpe[t] * buf[(r2 + t) % CONVK];
            C[r2 * 256 + m] = a;
            if (r2 < 63) {
                int row = r2 + 24;
                buf[r2 % CONVK] = S[row * 256 + (m ^ ((row & 7) << 2))];
            }
        }
    }
    __syncthreads();

    // ---- phase 4: V copy (over dead S) + softmax (C -> bf16 hi/lo P frags)
    #pragma unroll
    for (int i = 0; i < 8; i++) {
        int idx = tid + i * 256;
        int r = idx >> 3, ch = idx & 7;
        *(uint4*)(sVh + r * 72 + ch * 8) = *(const uint4*)(gVh + r * HD + ch * 8);
        *(uint4*)(sVl + r * 72 + ch * 8) = *(const uint4*)(gVl + r * HD + ch * 8);
    }
    #pragma unroll
    for (int rr = 0; rr < 8; rr++) {
        int r2 = warp * 8 + rr;
        float v[8];
        float mx = -1e30f;
        #pragma unroll
        for (int q = 0; q < 8; q++) {
            v[q] = C[r2 * 256 + lane + q * 32];
            mx = fmaxf(mx, v[q]);
        }
        #pragma unroll
        for (int o = 16; o > 0; o >>= 1)
            mx = fmaxf(mx, __shfl_xor_sync(0xffffffffu, mx, o));
        float ssum = 0.f;
        #pragma unroll
        for (int q = 0; q < 8; q++) {
            float e = __expf(v[q] - mx);
            ssum += e;
            bf16 eh, el;
            bf_split(e, eh, el);
            sPh[r2 * 264 + lane + q * 32] = eh;
            sPl[r2 * 264 + lane + q * 32] = el;
        }
        #pragma unroll
        for (int o = 16; o > 0; o >>= 1)
            ssum += __shfl_xor_sync(0xffffffffu, ssum, o);
        if (lane == 0) rowsum[r2] = ssum;
    }
    __syncthreads();

    // ---- phase 5: O[64][64] = P V (3-pass), normalize, write Ahi/Alo
    {
        int wm = warp >> 1, wn = warp & 1;            // 4 x 2 warps, tile 16x32
        float acc[4][4] = {};
        uint32_t ao = (uint32_t)(((wm * 16 + (lane & 15)) * 264 + (lane >> 4) * 8) * 2);
        #pragma unroll
        for (int c = 0; c < 16; c++) {
            uint32_t ah[4], al[4];
            uint32_t ad = sbase + FA_PH + ao + (uint32_t)(c * 16 * 2);
            ldsm_x4(ah, ad);
            ldsm_x4(al, ad + (FA_PL - FA_PH));
            uint32_t bh[4][2], bl[4][2];
            uint32_t brow = (uint32_t)(((c * 16 + (lane & 15)) * 72) * 2);
            #pragma unroll
            for (int ni = 0; ni < 4; ni++) {
                uint32_t bd = sbase + FA_VH + brow + (uint32_t)((wn * 32 + ni * 8) * 2);
                ldsm_x2_trans(bh[ni], bd);
                ldsm_x2_trans(bl[ni], bd + (FA_VL - FA_VH));
            }
            #pragma unroll
            for (int ni = 0; ni < 4; ni++) {
                mma_bf16(acc[ni], ah, bh[ni]);
                mma_bf16(acc[ni], ah, bl[ni]);
                mma_bf16(acc[ni], al, bh[ni]);
            }
        }
        int r2a = wm * 16 + (lane >> 2);
        float inva = 1.f / rowsum[r2a];
        float invb = 1.f / rowsum[r2a + 8];
        size_t rowA = ((size_t)(w * NTOK + n0 + r2a)) * DIMC + hh * HD;
        size_t rowB = ((size_t)(w * NTOK + n0 + r2a + 8)) * DIMC + hh * HD;
        #pragma unroll
        for (int ni = 0; ni < 4; ni++) {
            int d = wn * 32 + ni * 8 + (lane & 3) * 2;
            bf16 h0, l0, h1, l1;
            bf_split(acc[ni][0] * inva, h0, l0);
            bf_split(acc[ni][1] * inva, h1, l1);
            *(uint32_t*)(g_Ahb + rowA + d) = bpack(h0, h1);
            *(uint32_t*)(g_Alb + rowA + d) = bpack(l0, l1);
            bf_split(acc[ni][2] * invb, h0, l0);
            bf_split(acc[ni][3] * invb, h1, l1);
            *(uint32_t*)(g_Ahb + rowB + d) = bpack(h0, h1);
            *(uint32_t*)(g_Alb + rowB + d) = bpack(l0, l1);
        }
    }
}

// ---------------------------------------------------------------------------
extern "C" void kernel_launch(void* const* d_in, const int* in_sizes, int n_in,
                              void* d_out, int out_size) {
    const float* x       = (const float*)d_in[0];
    const float* qkv_w   = (const float*)d_in[1];
    const float* qkv_b   = (const float*)d_in[2];
    const float* proj_w  = (const float*)d_in[3];
    const float* proj_b  = (const float*)d_in[4];
    const float* table   = (const float*)d_in[5];
    const float* pe_w    = (const float*)d_in[6];
    const float* pe_b    = (const float*)d_in[7];
    const int*   rel_idx = (const int*)d_in[8];
    float* out = (float*)d_out;

    cudaFuncSetAttribute(mgemm_kernel<0>,
                         cudaFuncAttributeMaxDynamicSharedMemorySize, MG_SMEM);
    cudaFuncSetAttribute(mgemm_kernel<1>,
                         cudaFuncAttributeMaxDynamicSharedMemorySize, MG_SMEM);
    cudaFuncSetAttribute(fattn_kernel,
                         cudaFuncAttributeMaxDynamicSharedMemorySize, FA_SMEM);

    bf16 *Wh, *Wl, *PWh, *PWl;
    cudaGetSymbolAddress((void**)&Wh,  g_Whb);
    cudaGetSymbolAddress((void**)&Wl,  g_Wlb);
    cudaGetSymbolAddress((void**)&PWh, g_PWhb);
    cudaGetSymbolAddress((void**)&PWl, g_PWlb);

    bias_kernel<<<HEADS * NTOK, 256>>>(table, rel_idx);
    split_x_kernel<<<NWIN * NTOK, 128>>>(x);
    split_plain_kernel<<<(3 * DIMC * DIMC) / 1024, 256>>>(qkv_w, Wh, Wl);
    split_plain_kernel<<<(DIMC * DIMC) / 1024, 256>>>(proj_w, PWh, PWl);

    mgemm_kernel<0><<<dim3(256, 12), 256, MG_SMEM>>>(Wh, Wl, qkv_b, nullptr);
    fattn_kernel<<<dim3(WH, 4), 256, FA_SMEM>>>(pe_w, pe_b);
    mgemm_kernel<1><<<dim3(256, 4), 256, MG_SMEM>>>(PWh, PWl, proj_b, out);
}

// round 9
// speedup vs baseline: 4.0324x; 1.0143x over previous
#include <cuda_runtime.h>
#include <cuda_bf16.h>
#include <cstdint>
#include <math.h>

// Problem constants
#define B_IMG   8
#define LTOK    4096
#define DIMC    512
#define HEADS   8
#define HD      64
#define NTOK    256           // tokens per window (16x16)
#define NWIN    128           // B * 16 windows
#define WH      (NWIN*HEADS)  // 1024
#define QSCALE  0.125f        // 64^-0.5
#define CONVK   15

typedef __nv_bfloat16 bf16;

__device__ __forceinline__ uint32_t smem_to_u32(const void* p) {
    uint32_t a;
    asm("{ .reg .u64 t; cvta.to.shared.u64 t, %1; cvt.u32.u64 %0, t; }"
        : "=r"(a) : "l"(p));
    return a;
}

// cp.async helpers (sm_80+, arch-neutral PTX)
__device__ __forceinline__ void cp16(uint32_t dst, const void* src) {
    asm volatile("cp.async.cg.shared.global [%0], [%1], 16;"
                 :: "r"(dst), "l"(src));
}
__device__ __forceinline__ void cp16_pred(uint32_t dst, const void* src, bool v) {
    int sz = v ? 16 : 0;
    asm volatile("cp.async.cg.shared.global [%0], [%1], 16, %2;"
                 :: "r"(dst), "l"(src), "r"(sz));
}
#define CP_COMMIT() asm volatile("cp.async.commit_group;" ::: "memory")
#define CP_WAIT(N)  asm volatile("cp.async.wait_group %0;" :: "n"(N) : "memory")

// --------- device scratch (static allocations only; no cudaMalloc) ---------
__device__ float g_bias[HEADS*NTOK*NTOK];      // 2 MB   gathered rel-pos bias
__device__ bf16  g_Ahb[NWIN*NTOK*DIMC];        // 32 MB  A hi (x, then O)
__device__ bf16  g_Alb[NWIN*NTOK*DIMC];        // 32 MB  A lo residual
__device__ bf16  g_Whb[3*DIMC*DIMC];           // qkv weights hi
__device__ bf16  g_Wlb[3*DIMC*DIMC];
__device__ bf16  g_PWhb[DIMC*DIMC];            // proj weights hi
__device__ bf16  g_PWlb[DIMC*DIMC];
__device__ bf16  g_Qh[WH*NTOK*HD];             // 16 MB each: Q/K/V hi+lo
__device__ bf16  g_Ql[WH*NTOK*HD];
__device__ bf16  g_Kh[WH*NTOK*HD];
__device__ bf16  g_Kl[WH*NTOK*HD];
__device__ bf16  g_Vh[WH*NTOK*HD];
__device__ bf16  g_Vl[WH*NTOK*HD];

// window/token -> flat token index in (B, L) layout
__device__ __forceinline__ int win_tok_to_l(int w, int n) {
    int ww = w & 15;
    int rh = ww >> 2, rw = ww & 3;
    int i  = n >> 4,  j  = n & 15;
    return ((rh * 16 + i) << 6) + rw * 16 + j;
}

// bf16 hi/lo split
__device__ __forceinline__ void bf_split(float v, bf16& hi, bf16& lo) {
    hi = __float2bfloat16_rn(v);
    lo = __float2bfloat16_rn(v - __bfloat162float(hi));
}
__device__ __forceinline__ uint32_t bpack(bf16 a, bf16 b) {
    uint16_t xa = *(uint16_t*)&a, xb = *(uint16_t*)&b;
    return (uint32_t)xa | ((uint32_t)xb << 16);
}

// --------------------------- K0: bias gather -------------------------------
__global__ void bias_kernel(const float* __restrict__ table,
                            const int*   __restrict__ rel_index) {
    int hn = blockIdx.x;
    int hh = hn >> 8, n = hn & 255;
    int m  = threadIdx.x;
    int idx = rel_index[n * NTOK + m];
    g_bias[(size_t)hn * NTOK + m] = table[idx * HEADS + hh];
}

// ------------------- split kernels (fp32 -> bf16 hi + lo) ------------------
__global__ __launch_bounds__(128) void split_x_kernel(const float* __restrict__ x) {
    int r = blockIdx.x;                 // 0..32767 = w*256+n
    int w = r >> 8, n = r & 255;
    int l = win_tok_to_l(w, n);
    const float4* src = (const float4*)(x + ((size_t)((w >> 4) * LTOK + l)) * DIMC);
    float4 v = src[threadIdx.x];
    bf16 h4[4], l4[4];
    bf_split(v.x, h4[0], l4[0]); bf_split(v.y, h4[1], l4[1]);
    bf_split(v.z, h4[2], l4[2]); bf_split(v.w, h4[3], l4[3]);
    *(uint2*)(g_Ahb + (size_t)r * DIMC + threadIdx.x * 4) = *(uint2*)h4;
    *(uint2*)(g_Alb + (size_t)r * DIMC + threadIdx.x * 4) = *(uint2*)l4;
}

__global__ __launch_bounds__(256) void split_plain_kernel(const float* __restrict__ src,
                                                          bf16* __restrict__ hi,
                                                          bf16* __restrict__ lo) {
    size_t i = (size_t)blockIdx.x * 256 + threadIdx.x;
    float4 v = ((const float4*)src)[i];
    bf16 h4[4], l4[4];
    bf_split(v.x, h4[0], l4[0]); bf_split(v.y, h4[1], l4[1]);
    bf_split(v.z, h4[2], l4[2]); bf_split(v.w, h4[3], l4[3]);
    *(uint2*)(hi + i * 4) = *(uint2*)h4;
    *(uint2*)(lo + i * 4) = *(uint2*)l4;
}

// --------------------------- mma primitives --------------------------------
__device__ __forceinline__ void ldsm_x4(uint32_t* r, uint32_t addr) {
    asm volatile("ldmatrix.sync.aligned.m8n8.x4.shared.b16 {%0,%1,%2,%3}, [%4];"
                 : "=r"(r[0]), "=r"(r[1]), "=r"(r[2]), "=r"(r[3]) : "r"(addr));
}
__device__ __forceinline__ void ldsm_x2(uint32_t* r, uint32_t addr) {
    asm volatile("ldmatrix.sync.aligned.m8n8.x2.shared.b16 {%0,%1}, [%2];"
                 : "=r"(r[0]), "=r"(r[1]) : "r"(addr));
}
__device__ __forceinline__ void ldsm_x2_trans(uint32_t* r, uint32_t addr) {
    asm volatile("ldmatrix.sync.aligned.m8n8.x2.trans.shared.b16 {%0,%1}, [%2];"
                 : "=r"(r[0]), "=r"(r[1]) : "r"(addr));
}
__device__ __forceinline__ void mma_bf16(float* c, const uint32_t* a, const uint32_t* b) {
    asm volatile(
        "mma.sync.aligned.m16n8k16.row.col.f32.bf16.bf16.f32 "
        "{%0,%1,%2,%3}, {%4,%5,%6,%7}, {%8,%9}, {%0,%1,%2,%3};"
        : "+f"(c[0]), "+f"(c[1]), "+f"(c[2]), "+f"(c[3])
        : "r"(a[0]), "r"(a[1]), "r"(a[2]), "r"(a[3]), "r"(b[0]), "r"(b[1]));
}

// ------------- mma.sync bf16 3-pass GEMM: C = A * B^T + bias ---------------
// 4-stage cp.async pipeline, one barrier per K-chunk.
#define MG_STRIDE  24                      // bf16 elems per smem row (48 B)
#define MG_MTILE   (128*MG_STRIDE)         // one matrix tile: 3072 elems
#define MG_STAGE_E (4*MG_MTILE)            // Ah|Al|Bh|Bl per stage: 12288 elems
#define MG_STAGES  4
#define MG_SMEM    (MG_STAGES*MG_STAGE_E*2)   // 98304 B

template <int MODE>
__global__ __launch_bounds__(256, 1)
void mgemm_kernel(const bf16* __restrict__ Bh_g, const bf16* __restrict__ Bl_g,
                  const float* __restrict__ bias, float* __restrict__ outp) {
    extern __shared__ bf16 smem[];
    int tid  = threadIdx.x;
    int lane = tid & 31, warp = tid >> 5;
    int wm = warp & 1, wn = warp >> 1;
    int m0 = blockIdx.x * 128;
    int n0 = blockIdx.y * 128;

    int ldrow = tid >> 1;
    int ldk   = (tid & 1) * 8;

    const bf16* gA_h = g_Ahb + (size_t)(m0 + ldrow) * DIMC + ldk;
    const bf16* gA_l = g_Alb + (size_t)(m0 + ldrow) * DIMC + ldk;
    const bf16* gB_h = Bh_g + (size_t)(n0 + ldrow) * DIMC + ldk;
    const bf16* gB_l = Bl_g + (size_t)(n0 + ldrow) * DIMC + ldk;

    uint32_t sbase = smem_to_u32(smem);
    uint32_t sdst  = sbase + (uint32_t)((ldrow * MG_STRIDE + ldk) * 2);

    auto issue = [&](int c) {
        int s = c & 3;
        uint32_t d = sdst + (uint32_t)(s * MG_STAGE_E * 2);
        int k0 = c * 16;
        cp16(d,                   gA_h + k0);
        cp16(d + MG_MTILE*2,      gA_l + k0);
        cp16(d + 2*MG_MTILE*2,    gB_h + k0);
        cp16(d + 3*MG_MTILE*2,    gB_l + k0);
        CP_COMMIT();
    };

    const int NC = DIMC / 16;   // 32
    issue(0); issue(1); issue(2);

    float acc[4][4][4] = {};
    uint32_t aoff = (uint32_t)(((wm * 64 + (lane & 15)) * MG_STRIDE + (lane >> 4) * 8) * 2);
    uint32_t boff = (uint32_t)(((wn * 32 + (lane & 7)) * MG_STRIDE + ((lane >> 3) & 1) * 8) * 2);

    for (int c = 0; c < NC; c++) {
        if (c < NC - 2)      CP_WAIT(2);
        else if (c == NC - 2) CP_WAIT(1);
        else                  CP_WAIT(0);
        __syncthreads();
        if (c + 3 < NC) issue(c + 3);

        uint32_t st = sbase + (uint32_t)((c & 3) * MG_STAGE_E * 2);
        uint32_t ah[4][4], al[4][4], bh[4][2], bl[4][2];
        #pragma unroll
        for (int mi = 0; mi < 4; mi++) {
            uint32_t ad = st + aoff + (uint32_t)(mi * 16 * MG_STRIDE * 2);
            ldsm_x4(ah[mi], ad);
            ldsm_x4(al[mi], ad + MG_MTILE * 2);
        }
        #pragma unroll
        for (int ni = 0; ni < 4; ni++) {
            uint32_t bd = st + boff + (uint32_t)((2 * MG_MTILE + ni * 8 * MG_STRIDE) * 2);
            ldsm_x2(bh[ni], bd);
            ldsm_x2(bl[ni], bd + MG_MTILE * 2);
        }
        #pragma unroll
        for (int mi = 0; mi < 4; mi++)
            #pragma unroll
            for (int ni = 0; ni < 4; ni++) {
                mma_bf16(acc[mi][ni], ah[mi], bh[ni]);
                mma_bf16(acc[mi][ni], ah[mi], bl[ni]);
                mma_bf16(acc[mi][ni], al[mi], bh[ni]);
            }
    }

    #pragma unroll
    for (int mi = 0; mi < 4; mi++) {
        int r0 = m0 + wm * 64 + mi * 16 + (lane >> 2);
        #pragma unroll
        for (int ni = 0; ni < 4; ni++) {
            int cb = n0 + wn * 32 + ni * 8 + (lane & 3) * 2;
            float b0 = bias[cb], b1 = bias[cb + 1];
            #pragma unroll
            for (int half = 0; half < 2; half++) {
                int r = r0 + half * 8;
                float v0 = acc[mi][ni][half * 2 + 0] + b0;
                float v1 = acc[mi][ni][half * 2 + 1] + b1;
                int w2 = r >> 8, n2 = r & 255;
                if (MODE == 0) {
                    int s = cb >> 9, hh = (cb >> 6) & 7, d = cb & 63;
                    float scl = (s == 0) ? QSCALE : 1.0f;
                    size_t o = (((size_t)(w2 * HEADS + hh)) * NTOK + n2) * HD + d;
                    bf16* dh = (s == 0 ? g_Qh : (s == 1 ? g_Kh : g_Vh)) + o;
                    bf16* dl = (s == 0 ? g_Ql : (s == 1 ? g_Kl : g_Vl)) + o;
                    bf16 h0, l0, h1, l1;
                    bf_split(v0 * scl, h0, l0);
                    bf_split(v1 * scl, h1, l1);
                    *(uint32_t*)dh = bpack(h0, h1);
                    *(uint32_t*)dl = bpack(l0, l1);
                } else {
                    int l = win_tok_to_l(w2, n2);
                    float* dst = outp + ((size_t)((w2 >> 4) * LTOK + l)) * DIMC + cb;
                    float2 v = {v0, v1};
                    *(float2*)dst = v;
                }
            }
        }
    }
}

// ========== fused attention: S=QK^T -> conv -> softmax -> PV (all mma) =====
#define FA_S    0        // fp32 [96][256]  98304   (phase 1-2; then Vh/Vl)
#define FA_QH   98304    // bf16 [96][72]   13824
#define FA_QL   112128
#define FA_KH   125952   // bf16 [256][72]  36864
#define FA_KL   162816   //                 (ends 199680)
#define FA_C    98304    // fp32 [64][256]  65536   (phase 3-4, over Q/K)
#define FA_VH   0        // bf16 [256][72]  36864   (phase 4+, over S)
#define FA_VL   36864
#define FA_PH   163840   // bf16 [64][264]  33792
#define FA_PL   197632   //                 (ends 231424)
#define FA_RS   231424   // fp32 [64]
#define FA_SMEM 231680

__global__ __launch_bounds__(256, 1)
void fattn_kernel(const float* __restrict__ pew, const float* __restrict__ peb) {
    extern __shared__ char fsm[];
    float* S  = (float*)(fsm + FA_S);
    float* C  = (float*)(fsm + FA_C);
    bf16* sPh = (bf16*)(fsm + FA_PH);
    bf16* sPl = (bf16*)(fsm + FA_PL);
    float* rowsum = (float*)(fsm + FA_RS);

    int wh = blockIdx.x;
    int n0 = blockIdx.y * 64;
    int hh = wh & 7, w = wh >> 3;
    int tid = threadIdx.x, lane = tid & 31, warp = tid >> 5;
    uint32_t sbase = smem_to_u32(fsm);

    const bf16* gQh = g_Qh + (size_t)wh * NTOK * HD;
    const bf16* gQl = g_Ql + (size_t)wh * NTOK * HD;
    const bf16* gKh = g_Kh + (size_t)wh * NTOK * HD;
    const bf16* gKl = g_Kl + (size_t)wh * NTOK * HD;
    const bf16* gVh = g_Vh + (size_t)wh * NTOK * HD;
    const bf16* gVl = g_Vl + (size_t)wh * NTOK * HD;

    // ---- phase 1: cp.async Q halo (zfill out-of-window) + K tiles
    #pragma unroll
    for (int i = 0; i < 3; i++) {
        int idx = tid + i * 256;
        int r = idx >> 3, ch = idx & 7;
        int n = n0 + r - 16;
        bool ok = (n >= 0 && n < NTOK);
        int nc = ok ? n : 0;
        uint32_t dq = sbase + (uint32_t)((r * 72 + ch * 8) * 2);
        cp16_pred(dq + FA_QH, gQh + nc * HD + ch * 8, ok);
        cp16_pred(dq + FA_QL, gQl + nc * HD + ch * 8, ok);
    }
    #pragma unroll
    for (int i = 0; i < 8; i++) {
        int idx = tid + i * 256;
        int r = idx >> 3, ch = idx & 7;
        uint32_t dk = sbase + (uint32_t)((r * 72 + ch * 8) * 2);
        cp16(dk + FA_KH, gKh + r * HD + ch * 8);
        cp16(dk + FA_KL, gKl + r * HD + ch * 8);
    }
    CP_COMMIT();
    CP_WAIT(0);
    __syncthreads();

    // ---- phase 2: S[96][256] = Q K^T, 3-pass mma, XOR-swizzled fp32 store
    {
        int wm = warp & 1, wn = warp >> 1;            // 2 x 4 warps, tile 48x64
        float acc[3][8][4] = {};
        uint32_t ao = (uint32_t)(((wm * 48 + (lane & 15)) * 72 + (lane >> 4) * 8) * 2);
        uint32_t bo = (uint32_t)(((wn * 64 + (lane & 7)) * 72 + ((lane >> 3) & 1) * 8) * 2);
        #pragma unroll
        for (int c = 0; c < 4; c++) {
            uint32_t ah[3][4], al[3][4], bh[8][2], bl[8][2];
            #pragma unroll
            for (int mi = 0; mi < 3; mi++) {
                uint32_t ad = sbase + FA_QH + ao + (uint32_t)((mi * 16 * 72 + c * 16) * 2);
                ldsm_x4(ah[mi], ad);
                ldsm_x4(al[mi], ad + (FA_QL - FA_QH));
            }
            #pragma unroll
            for (int ni = 0; ni < 8; ni++) {
                uint32_t bd = sbase + FA_KH + bo + (uint32_t)((ni * 8 * 72 + c * 16) * 2);
                ldsm_x2(bh[ni], bd);
                ldsm_x2(bl[ni], bd + (FA_KL - FA_KH));
            }
            #pragma unroll
            for (int mi = 0; mi < 3; mi++)
                #pragma unroll
                for (int ni = 0; ni < 8; ni++) {
                    mma_bf16(acc[mi][ni], ah[mi], bh[ni]);
                    mma_bf16(acc[mi][ni], ah[mi], bl[ni]);
                    mma_bf16(acc[mi][ni], al[mi], bh[ni]);
                }
        }
        #pragma unroll
        for (int mi = 0; mi < 3; mi++) {
            int r = wm * 48 + mi * 16 + (lane >> 2);
            #pragma unroll
            for (int ni = 0; ni < 8; ni++) {
                int colb = wn * 64 + ni * 8 + (lane & 3) * 2;
                int c0 = colb ^ ((r & 7) << 2);
                float2 v0 = {acc[mi][ni][0], acc[mi][ni][1]};
                *(float2*)&S[r * 256 + c0] = v0;
                int r8 = r + 8;
                int c1 = colb ^ ((r8 & 7) << 2);
                float2 v1 = {acc[mi][ni][2], acc[mi][ni][3]};
                *(float2*)&S[r8 * 256 + c1] = v1;
            }
        }
    }
    __syncthreads();

    // ---- phase 3: 15-tap conv over query axis + pe bias + rel-pos bias
    {
        float wpe[CONVK];
        #pragma unroll
        for (int t = 0; t < CONVK; t++) wpe[t] = pew[hh * CONVK + t];
        float pbv = peb[hh];
        int m = tid;
        const float* bg = g_bias + ((size_t)hh * NTOK + n0) * NTOK + m;
        float buf[CONVK];                 // ring: row x at slot (x-9)%15
        #pragma unroll
        for (int t = 0; t < CONVK; t++) {
            int row = 9 + t;
            buf[t] = S[row * 256 + (m ^ ((row & 7) << 2))];
        }
        #pragma unroll
        for (int r2 = 0; r2 < 64; r2++) {
            float a = buf[(r2 + 7) % CONVK] + pbv + bg[r2 * 256];
            #pragma unroll
            for (int t = 0; t < CONVK; t++)
                a += wpe[t] * buf[(r2 + t) % CONVK];
            C[r2 * 256 + m] = a;
            if (r2 < 63) {
                int row = r2 + 24;
                buf[r2 % CONVK] = S[row * 256 + (m ^ ((row & 7) << 2))];
            }
        }
    }
    __syncthreads();

    // ---- phase 4: async V copy (over dead S) overlapped with softmax
    #pragma unroll
    for (int i = 0; i < 8; i++) {
        int idx = tid + i * 256;
        int r = idx >> 3, ch = idx & 7;
        uint32_t dv = sbase + (uint32_t)((r * 72 + ch * 8) * 2);
        cp16(dv + FA_VH, gVh + r * HD + ch * 8);
        cp16(dv + FA_VL, gVl + r * HD + ch * 8);
    }
    CP_COMMIT();
    #pragma unroll
    for (int rr = 0; rr < 8; rr++) {
        int r2 = warp * 8 + rr;
        float v[8];
        float mx = -1e30f;
        #pragma unroll
        for (int q = 0; q < 8; q++) {
            v[q] = C[r2 * 256 + lane + q * 32];
            mx = fmaxf(mx, v[q]);
        }
        #pragma unroll
        for (int o = 16; o > 0; o >>= 1)
            mx = fmaxf(mx, __shfl_xor_sync(0xffffffffu, mx, o));
        float ssum = 0.f;
        #pragma unroll
        for (int q = 0; q < 8; q++) {
            float e = __expf(v[q] - mx);
            ssum += e;
            bf16 eh, el;
            bf_split(e, eh, el);
            sPh[r2 * 264 + lane + q * 32] = eh;
            sPl[r2 * 264 + lane + q * 32] = el;
        }
        #pragma unroll
        for (int o = 16; o > 0; o >>= 1)
            ssum += __shfl_xor_sync(0xffffffffu, ssum, o);
        if (lane == 0) rowsum[r2] = ssum;
    }
    CP_WAIT(0);
    __syncthreads();

    // ---- phase 5: O[64][64] = P V (3-pass), normalize, write Ahi/Alo
    {
        int wm = warp >> 1, wn = warp & 1;            // 4 x 2 warps, tile 16x32
        float acc[4][4] = {};
        uint32_t ao = (uint32_t)(((wm * 16 + (lane & 15)) * 264 + (lane >> 4) * 8) * 2);
        #pragma unroll
        for (int c = 0; c < 16; c++) {
            uint32_t ah[4], al[4];
            uint32_t ad = sbase + FA_PH + ao + (uint32_t)(c * 16 * 2);
            ldsm_x4(ah, ad);
            ldsm_x4(al, ad + (FA_PL - FA_PH));
            uint32_t bh[4][2], bl[4][2];
            uint32_t brow = (uint32_t)(((c * 16 + (lane & 15)) * 72) * 2);
            #pragma unroll
            for (int ni = 0; ni < 4; ni++) {
                uint32_t bd = sbase + FA_VH + brow + (uint32_t)((wn * 32 + ni * 8) * 2);
                ldsm_x2_trans(bh[ni], bd);
                ldsm_x2_trans(bl[ni], bd + (FA_VL - FA_VH));
            }
            #pragma unroll
            for (int ni = 0; ni < 4; ni++) {
                mma_bf16(acc[ni], ah, bh[ni]);
                mma_bf16(acc[ni], ah, bl[ni]);
                mma_bf16(acc[ni], al, bh[ni]);
            }
        }
        int r2a = wm * 16 + (lane >> 2);
        float inva = 1.f / rowsum[r2a];
        float invb = 1.f / rowsum[r2a + 8];
        size_t rowA = ((size_t)(w * NTOK + n0 + r2a)) * DIMC + hh * HD;
        size_t rowB = ((size_t)(w * NTOK + n0 + r2a + 8)) * DIMC + hh * HD;
        #pragma unroll
        for (int ni = 0; ni < 4; ni++) {
            int d = wn * 32 + ni * 8 + (lane & 3) * 2;
            bf16 h0, l0, h1, l1;
            bf_split(acc[ni][0] * inva, h0, l0);
            bf_split(acc[ni][1] * inva, h1, l1);
            *(uint32_t*)(g_Ahb + rowA + d) = bpack(h0, h1);
            *(uint32_t*)(g_Alb + rowA + d) = bpack(l0, l1);
            bf_split(acc[ni][2] * invb, h0, l0);
            bf_split(acc[ni][3] * invb, h1, l1);
            *(uint32_t*)(g_Ahb + rowB + d) = bpack(h0, h1);
            *(uint32_t*)(g_Alb + rowB + d) = bpack(l0, l1);
        }
    }
}

// ---------------------------------------------------------------------------
extern "C" void kernel_launch(void* const* d_in, const int* in_sizes, int n_in,
                              void* d_out, int out_size) {
    const float* x       = (const float*)d_in[0];
    const float* qkv_w   = (const float*)d_in[1];
    const float* qkv_b   = (const float*)d_in[2];
    const float* proj_w  = (const float*)d_in[3];
    const float* proj_b  = (const float*)d_in[4];
    const float* table   = (const float*)d_in[5];
    const float* pe_w    = (const float*)d_in[6];
    const float* pe_b    = (const float*)d_in[7];
    const int*   rel_idx = (const int*)d_in[8];
    float* out = (float*)d_out;

    cudaFuncSetAttribute(mgemm_kernel<0>,
                         cudaFuncAttributeMaxDynamicSharedMemorySize, MG_SMEM);
    cudaFuncSetAttribute(mgemm_kernel<1>,
                         cudaFuncAttributeMaxDynamicSharedMemorySize, MG_SMEM);
    cudaFuncSetAttribute(fattn_kernel,
                         cudaFuncAttributeMaxDynamicSharedMemorySize, FA_SMEM);

    bf16 *Wh, *Wl, *PWh, *PWl;
    cudaGetSymbolAddress((void**)&Wh,  g_Whb);
    cudaGetSymbolAddress((void**)&Wl,  g_Wlb);
    cudaGetSymbolAddress((void**)&PWh, g_PWhb);
    cudaGetSymbolAddress((void**)&PWl, g_PWlb);

    bias_kernel<<<HEADS * NTOK, 256>>>(table, rel_idx);
    split_x_kernel<<<NWIN * NTOK, 128>>>(x);
    split_plain_kernel<<<(3 * DIMC * DIMC) / 1024, 256>>>(qkv_w, Wh, Wl);
    split_plain_kernel<<<(DIMC * DIMC) / 1024, 256>>>(proj_w, PWh, PWl);

    mgemm_kernel<0><<<dim3(256, 12), 256, MG_SMEM>>>(Wh, Wl, qkv_b, nullptr);
    fattn_kernel<<<dim3(WH, 4), 256, FA_SMEM>>>(pe_w, pe_b);
    mgemm_kernel<1><<<dim3(256, 4), 256, MG_SMEM>>>(PWh, PWl, proj_b, out);
}

// round 10
// speedup vs baseline: 8.0859x; 2.0052x over previous
#include <cuda_runtime.h>
#include <cuda_fp16.h>
#include <cstdint>
#include <math.h>

// Problem constants
#define B_IMG   8
#define LTOK    4096
#define DIMC    512
#define HEADS   8
#define HD      64
#define NTOK    256           // tokens per window (16x16)
#define NWIN    128           // B * 16 windows
#define WH      (NWIN*HEADS)  // 1024
#define QSCALE  0.125f        // 64^-0.5
#define CONVK   15

typedef __half fp16;

__device__ __forceinline__ uint32_t smem_to_u32(const void* p) {
    uint32_t a;
    asm("{ .reg .u64 t; cvta.to.shared.u64 t, %1; cvt.u32.u64 %0, t; }"
        : "=r"(a) : "l"(p));
    return a;
}

// cp.async helpers (sm_80+, arch-neutral PTX)
__device__ __forceinline__ void cp16(uint32_t dst, const void* src) {
    asm volatile("cp.async.cg.shared.global [%0], [%1], 16;"
                 :: "r"(dst), "l"(src));
}
__device__ __forceinline__ void cp16_pred(uint32_t dst, const void* src, bool v) {
    int sz = v ? 16 : 0;
    asm volatile("cp.async.cg.shared.global [%0], [%1], 16, %2;"
                 :: "r"(dst), "l"(src), "r"(sz));
}
#define CP_COMMIT() asm volatile("cp.async.commit_group;" ::: "memory")
#define CP_WAIT(N)  asm volatile("cp.async.wait_group %0;" :: "n"(N) : "memory")

// --------- device scratch (static allocations only; no cudaMalloc) ---------
__device__ float g_bias[HEADS*NTOK*NTOK];      // gathered rel-pos bias
__device__ fp16  g_X16[NWIN*NTOK*DIMC];        // gathered x (QKV A operand)
__device__ fp16  g_O16[NWIN*NTOK*DIMC];        // attention out (proj A operand)
__device__ fp16  g_W16[3*DIMC*DIMC];           // qkv weights
__device__ fp16  g_PW16[DIMC*DIMC];            // proj weights
__device__ fp16  g_Q16[WH*NTOK*HD];
__device__ fp16  g_K16[WH*NTOK*HD];
__device__ fp16  g_V16[WH*NTOK*HD];

// window/token -> flat token index in (B, L) layout
__device__ __forceinline__ int win_tok_to_l(int w, int n) {
    int ww = w & 15;
    int rh = ww >> 2, rw = ww & 3;
    int i  = n >> 4,  j  = n & 15;
    return ((rh * 16 + i) << 6) + rw * 16 + j;
}

__device__ __forceinline__ uint32_t hpack(float a, float b) {
    __half2 h = __floats2half2_rn(a, b);
    return *(uint32_t*)&h;
}

// --------------------------- K0: bias gather -------------------------------
__global__ void bias_kernel(const float* __restrict__ table,
                            const int*   __restrict__ rel_index) {
    int hn = blockIdx.x;
    int hh = hn >> 8, n = hn & 255;
    int m  = threadIdx.x;
    int idx = rel_index[n * NTOK + m];
    g_bias[(size_t)hn * NTOK + m] = table[idx * HEADS + hh];
}

// ------------------- convert kernels (fp32 -> fp16) ------------------------
__global__ __launch_bounds__(128) void cvt_x_kernel(const float* __restrict__ x) {
    int r = blockIdx.x;                 // 0..32767 = w*256+n
    int w = r >> 8, n = r & 255;
    int l = win_tok_to_l(w, n);
    const float4* src = (const float4*)(x + ((size_t)((w >> 4) * LTOK + l)) * DIMC);
    float4 v = src[threadIdx.x];
    uint2 o;
    o.x = hpack(v.x, v.y);
    o.y = hpack(v.z, v.w);
    *(uint2*)(g_X16 + (size_t)r * DIMC + threadIdx.x * 4) = o;
}

__global__ __launch_bounds__(256) void cvt_w_kernel(const float* __restrict__ src,
                                                    fp16* __restrict__ dst) {
    size_t i = (size_t)blockIdx.x * 256 + threadIdx.x;
    float4 v = ((const float4*)src)[i];
    uint2 o;
    o.x = hpack(v.x, v.y);
    o.y = hpack(v.z, v.w);
    *(uint2*)(dst + i * 4) = o;
}

// --------------------------- mma primitives --------------------------------
__device__ __forceinline__ void ldsm_x4(uint32_t* r, uint32_t addr) {
    asm volatile("ldmatrix.sync.aligned.m8n8.x4.shared.b16 {%0,%1,%2,%3}, [%4];"
                 : "=r"(r[0]), "=r"(r[1]), "=r"(r[2]), "=r"(r[3]) : "r"(addr));
}
__device__ __forceinline__ void ldsm_x2_trans(uint32_t* r, uint32_t addr) {
    asm volatile("ldmatrix.sync.aligned.m8n8.x2.trans.shared.b16 {%0,%1}, [%2];"
                 : "=r"(r[0]), "=r"(r[1]) : "r"(addr));
}
__device__ __forceinline__ void mma_fp16(float* c, const uint32_t* a, const uint32_t* b) {
    asm volatile(
        "mma.sync.aligned.m16n8k16.row.col.f32.f16.f16.f32 "
        "{%0,%1,%2,%3}, {%4,%5,%6,%7}, {%8,%9}, {%0,%1,%2,%3};"
        : "+f"(c[0]), "+f"(c[1]), "+f"(c[2]), "+f"(c[3])
        : "r"(a[0]), "r"(a[1]), "r"(a[2]), "r"(a[3]), "r"(b[0]), "r"(b[1]));
}

// -------------- mma.sync fp16 single-pass GEMM: C = A * B^T + bias ---------
// Block tile 128x256, 8 warps (2x4), warp tile 64x64, k-chunks of 16,
// 4-stage cp.async pipeline.
// MODE 0: A = g_X16; epilogue scatters fp16 to g_Q16 (*QSCALE)/g_K16/g_V16.
// MODE 1: A = g_O16; epilogue adds proj bias, region-reverse fp32 to out.
#define MG_STRIDE  24                       // fp16 elems per smem row (48 B)
#define MG_ABYTES  (128*MG_STRIDE*2)        // 6144
#define MG_BBYTES  (256*MG_STRIDE*2)        // 12288
#define MG_STAGE_B (MG_ABYTES + MG_BBYTES)  // 18432
#define MG_SMEM    (4*MG_STAGE_B)           // 73728

template <int MODE>
__global__ __launch_bounds__(256, 1)
void mgemm_kernel(const fp16* __restrict__ Bw, const float* __restrict__ bias,
                  float* __restrict__ outp) {
    extern __shared__ char smem[];
    int tid  = threadIdx.x;
    int lane = tid & 31, warp = tid >> 5;
    int wm = warp & 1, wn = warp >> 1;
    int m0 = blockIdx.x * 128;
    int n0 = blockIdx.y * 256;

    const fp16* gA = (MODE == 0 ? g_X16 : g_O16) + (size_t)m0 * DIMC;
    const fp16* gB = Bw + (size_t)n0 * DIMC;

    uint32_t sbase = smem_to_u32(smem);

    auto issue = [&](int c) {
        uint32_t base = sbase + (uint32_t)((c & 3) * MG_STAGE_B);
        int k0 = c * 16;
        {   // A: 128 rows x 16 fp16, 1 cp per thread
            int row = tid >> 1, half = tid & 1;
            cp16(base + (uint32_t)((row * MG_STRIDE + half * 8) * 2),
                 gA + (size_t)row * DIMC + k0 + half * 8);
        }
        #pragma unroll
        for (int i = 0; i < 2; i++) {   // B: 256 rows x 16 fp16
            int idx = tid + i * 256;
            int row = idx >> 1, half = idx & 1;
            cp16(base + MG_ABYTES + (uint32_t)((row * MG_STRIDE + half * 8) * 2),
                 gB + (size_t)row * DIMC + k0 + half * 8);
        }
        CP_COMMIT();
    };

    const int NC = DIMC / 16;   // 32
    issue(0); issue(1); issue(2);

    float acc[4][8][4] = {};
    uint32_t aoff = (uint32_t)(((wm * 64 + (lane & 15)) * MG_STRIDE + (lane >> 4) * 8) * 2);
    int tq = lane >> 3;   // 0..3 (x4 B tile select)
    uint32_t boff = (uint32_t)(((wn * 64 + ((tq >> 1) << 3) + (lane & 7)) * MG_STRIDE
                                + (tq & 1) * 8) * 2);

    for (int c = 0; c < NC; c++) {
        if (c < NC - 2)       CP_WAIT(2);
        else if (c == NC - 2) CP_WAIT(1);
        else                  CP_WAIT(0);
        __syncthreads();
        if (c + 3 < NC) issue(c + 3);

        uint32_t st = sbase + (uint32_t)((c & 3) * MG_STAGE_B);
        uint32_t a[4][4], bf[16];
        #pragma unroll
        for (int mi = 0; mi < 4; mi++)
            ldsm_x4(a[mi], st + aoff + (uint32_t)(mi * 16 * MG_STRIDE * 2));
        #pragma unroll
        for (int p = 0; p < 4; p++)
            ldsm_x4(&bf[p * 4], st + MG_ABYTES + boff
                                + (uint32_t)(p * 16 * MG_STRIDE * 2));
        #pragma unroll
        for (int mi = 0; mi < 4; mi++)
            #pragma unroll
            for (int ni = 0; ni < 8; ni++)
                mma_fp16(acc[mi][ni], a[mi], &bf[ni * 2]);
    }

    #pragma unroll
    for (int mi = 0; mi < 4; mi++) {
        int r0 = m0 + wm * 64 + mi * 16 + (lane >> 2);
        #pragma unroll
        for (int ni = 0; ni < 8; ni++) {
            int cb = n0 + wn * 64 + ni * 8 + (lane & 3) * 2;
            float b0 = bias[cb], b1 = bias[cb + 1];
            #pragma unroll
            for (int half = 0; half < 2; half++) {
                int r = r0 + half * 8;
                float v0 = acc[mi][ni][half * 2 + 0] + b0;
                float v1 = acc[mi][ni][half * 2 + 1] + b1;
                int w2 = r >> 8, n2 = r & 255;
                if (MODE == 0) {
                    int s = cb >> 9, hh = (cb >> 6) & 7, d = cb & 63;
                    float scl = (s == 0) ? QSCALE : 1.0f;
                    size_t o = (((size_t)(w2 * HEADS + hh)) * NTOK + n2) * HD + d;
                    fp16* dh = (s == 0 ? g_Q16 : (s == 1 ? g_K16 : g_V16)) + o;
                    *(uint32_t*)dh = hpack(v0 * scl, v1 * scl);
                } else {
                    int l = win_tok_to_l(w2, n2);
                    float* dst = outp + ((size_t)((w2 >> 4) * LTOK + l)) * DIMC + cb;
                    float2 v = {v0, v1};
                    *(float2*)dst = v;
                }
            }
        }
    }
}

// ========== fused attention: S=QK^T -> conv -> softmax -> PV (fp16 mma) ====
// one block = (window*head, 64-query tile). S halo 96 rows (mma-aligned).
// smem byte offsets (total 115968, overlaid by phase):
#define FA_S    0        // fp16 [96][256] swizzled  49152  (then V)
#define FA_Q    49152    // fp16 [96][72]            13824
#define FA_K    62976    // fp16 [256][72]           36864  (ends 99840)
#define FA_C    49152    // fp16 [64][256]           32768  (phase 3+, over Q/K)
#define FA_V    0        // fp16 [256][72]           36864  (phase 4+, over S)
#define FA_P    81920    // fp16 [64][264]           33792  (ends 115712)
#define FA_RS   115712   // fp32 [64]
#define FA_SMEM 115968

__global__ __launch_bounds__(256, 1)
void fattn_kernel(const float* __restrict__ pew, const float* __restrict__ peb) {
    extern __shared__ char fsm[];
    uint32_t* S32 = (uint32_t*)(fsm + FA_S);    // [96][128] u32 (fp16 pairs)
    fp16* Ch  = (fp16*)(fsm + FA_C);
    fp16* sPh = (fp16*)(fsm + FA_P);
    float* rowsum = (float*)(fsm + FA_RS);

    int wh = blockIdx.x;
    int n0 = blockIdx.y * 64;
    int hh = wh & 7, w = wh >> 3;
    int tid = threadIdx.x, lane = tid & 31, warp = tid >> 5;
    uint32_t sbase = smem_to_u32(fsm);

    const fp16* gQ = g_Q16 + (size_t)wh * NTOK * HD;
    const fp16* gK = g_K16 + (size_t)wh * NTOK * HD;
    const fp16* gV = g_V16 + (size_t)wh * NTOK * HD;

    // ---- phase 1: cp.async Q halo (zfill out-of-window) + K tiles
    #pragma unroll
    for (int i = 0; i < 3; i++) {       // Q: 96 rows x 64 fp16 (8 cp per row)
        int idx = tid + i * 256;
        int r = idx >> 3, ch = idx & 7;
        int n = n0 + r - 16;
        bool ok = (n >= 0 && n < NTOK);
        int nc = ok ? n : 0;
        cp16_pred(sbase + FA_Q + (uint32_t)((r * 72 + ch * 8) * 2),
                  gQ + nc * HD + ch * 8, ok);
    }
    #pragma unroll
    for (int i = 0; i < 8; i++) {       // K: 256 rows
        int idx = tid + i * 256;
        int r = idx >> 3, ch = idx & 7;
        cp16(sbase + FA_K + (uint32_t)((r * 72 + ch * 8) * 2),
             gK + r * HD + ch * 8);
    }
    CP_COMMIT();
    CP_WAIT(0);
    __syncthreads();

    // ---- phase 2: S[96][256] = Q K^T (single-pass), swizzled fp16 store
    {
        int wm = warp & 1, wn = warp >> 1;            // 2 x 4 warps, tile 48x64
        float acc[3][8][4] = {};
        uint32_t ao = sbase + FA_Q +
            (uint32_t)(((wm * 48 + (lane & 15)) * 72 + (lane >> 4) * 8) * 2);
        int tq = lane >> 3;
        uint32_t bo = sbase + FA_K +
            (uint32_t)(((wn * 64 + ((tq >> 1) << 3) + (lane & 7)) * 72 + (tq & 1) * 8) * 2);
        #pragma unroll
        for (int c = 0; c < 4; c++) {
            uint32_t a[3][4], bf[16];
            #pragma unroll
            for (int mi = 0; mi < 3; mi++)
                ldsm_x4(a[mi], ao + (uint32_t)((mi * 16 * 72 + c * 16) * 2));
            #pragma unroll
            for (int p = 0; p < 4; p++)
                ldsm_x4(&bf[p * 4], bo + (uint32_t)((p * 16 * 72 + c * 16) * 2));
            #pragma unroll
            for (int mi = 0; mi < 3; mi++)
                #pragma unroll
                for (int ni = 0; ni < 8; ni++)
                    mma_fp16(acc[mi][ni], a[mi], &bf[ni * 2]);
        }
        #pragma unroll
        for (int mi = 0; mi < 3; mi++) {
            int r = wm * 48 + mi * 16 + (lane >> 2);
            int r8 = r + 8;
            #pragma unroll
            for (int ni = 0; ni < 8; ni++) {
                int wrd = wn * 32 + ni * 4 + (lane & 3);
                S32[r  * 128 + (wrd ^ ((r  & 7) << 2))] = hpack(acc[mi][ni][0], acc[mi][ni][1]);
                S32[r8 * 128 + (wrd ^ ((r8 & 7) << 2))] = hpack(acc[mi][ni][2], acc[mi][ni][3]);
            }
        }
    }
    __syncthreads();

    // ---- phase 3: 15-tap conv over query axis + pe bias + rel-pos bias
    {
        float wpe[CONVK];
        #pragma unroll
        for (int t = 0; t < CONVK; t++) wpe[t] = pew[hh * CONVK + t];
        float pbv = peb[hh];
        int m = tid;
        int mw = m >> 1, mh = m & 1;
        const float* bg = g_bias + ((size_t)hh * NTOK + n0) * NTOK + m;
        float buf[CONVK];                 // ring: row x at slot (x-9)%15
        #pragma unroll
        for (int t = 0; t < CONVK; t++) {
            int row = 9 + t;
            uint32_t v = S32[row * 128 + (mw ^ ((row & 7) << 2))];
            __half2 h2 = *(__half2*)&v;
            buf[t] = mh ? __high2float(h2) : __low2float(h2);
        }
        #pragma unroll
        for (int r2 = 0; r2 < 64; r2++) {
            float a = buf[(r2 + 7) % CONVK] + pbv + bg[r2 * 256];
            #pragma unroll
            for (int t = 0; t < CONVK; t++)
                a += wpe[t] * buf[(r2 + t) % CONVK];
            Ch[r2 * 256 + m] = __float2half_rn(a);
            if (r2 < 63) {
                int row = r2 + 24;
                uint32_t v = S32[row * 128 + (mw ^ ((row & 7) << 2))];
                __half2 h2 = *(__half2*)&v;
                buf[r2 % CONVK] = mh ? __high2float(h2) : __low2float(h2);
            }
        }
    }
    __syncthreads();

    // ---- phase 4: async V copy (over dead S) overlapped with softmax
    #pragma unroll
    for (int i = 0; i < 8; i++) {
        int idx = tid + i * 256;
        int r = idx >> 3, ch = idx & 7;
        cp16(sbase + FA_V + (uint32_t)((r * 72 + ch * 8) * 2),
             gV + r * HD + ch * 8);
    }
    CP_COMMIT();
    #pragma unroll
    for (int rr = 0; rr < 8; rr++) {
        int r2 = warp * 8 + rr;
        float v[8];
        float mx = -1e30f;
        #pragma unroll
        for (int q = 0; q < 8; q++) {
            v[q] = __half2float(Ch[r2 * 256 + lane + q * 32]);
            mx = fmaxf(mx, v[q]);
        }
        #pragma unroll
        for (int o = 16; o > 0; o >>= 1)
            mx = fmaxf(mx, __shfl_xor_sync(0xffffffffu, mx, o));
        float ssum = 0.f;
        #pragma unroll
        for (int q = 0; q < 8; q++) {
            float e = __expf(v[q] - mx);
            ssum += e;
            sPh[r2 * 264 + lane + q * 32] = __float2half_rn(e);
        }
        #pragma unroll
        for (int o = 16; o > 0; o >>= 1)
            ssum += __shfl_xor_sync(0xffffffffu, ssum, o);
        if (lane == 0) rowsum[r2] = ssum;
    }
    CP_WAIT(0);
    __syncthreads();

    // ---- phase 5: O[64][64] = P V (single-pass), normalize, write g_O16
    {
        int wm = warp >> 1, wn = warp & 1;            // 4 x 2 warps, tile 16x32
        float acc[4][4] = {};
        uint32_t ao = sbase + FA_P +
            (uint32_t)(((wm * 16 + (lane & 15)) * 264 + (lane >> 4) * 8) * 2);
        #pragma unroll
        for (int c = 0; c < 16; c++) {
            uint32_t a[4];
            ldsm_x4(a, ao + (uint32_t)(c * 16 * 2));
            uint32_t b[4][2];
            uint32_t brow = sbase + FA_V + (uint32_t)((c * 16 + (lane & 15)) * 72 * 2);
            #pragma unroll
            for (int ni = 0; ni < 4; ni++)
                ldsm_x2_trans(b[ni], brow + (uint32_t)((wn * 32 + ni * 8) * 2));
            #pragma unroll
            for (int ni = 0; ni < 4; ni++)
                mma_fp16(acc[ni], a, b[ni]);
        }
        int r2a = wm * 16 + (lane >> 2);
        float inva = 1.f / rowsum[r2a];
        float invb = 1.f / rowsum[r2a + 8];
        size_t rowA = ((size_t)(w * NTOK + n0 + r2a)) * DIMC + hh * HD;
        size_t rowB = ((size_t)(w * NTOK + n0 + r2a + 8)) * DIMC + hh * HD;
        #pragma unroll
        for (int ni = 0; ni < 4; ni++) {
            int d = wn * 32 + ni * 8 + (lane & 3) * 2;
            *(uint32_t*)(g_O16 + rowA + d) = hpack(acc[ni][0] * inva, acc[ni][1] * inva);
            *(uint32_t*)(g_O16 + rowB + d) = hpack(acc[ni][2] * invb, acc[ni][3] * invb);
        }
    }
}

// ---------------------------------------------------------------------------
extern "C" void kernel_launch(void* const* d_in, const int* in_sizes, int n_in,
                              void* d_out, int out_size) {
    const float* x       = (const float*)d_in[0];
    const float* qkv_w   = (const float*)d_in[1];
    const float* qkv_b   = (const float*)d_in[2];
    const float* proj_w  = (const float*)d_in[3];
    const float* proj_b  = (const float*)d_in[4];
    const float* table   = (const float*)d_in[5];
    const float* pe_w    = (const float*)d_in[6];
    const float* pe_b    = (const float*)d_in[7];
    const int*   rel_idx = (const int*)d_in[8];
    float* out = (float*)d_out;

    cudaFuncSetAttribute(mgemm_kernel<0>,
                         cudaFuncAttributeMaxDynamicSharedMemorySize, MG_SMEM);
    cudaFuncSetAttribute(mgemm_kernel<1>,
                         cudaFuncAttributeMaxDynamicSharedMemorySize, MG_SMEM);
    cudaFuncSetAttribute(fattn_kernel,
                         cudaFuncAttributeMaxDynamicSharedMemorySize, FA_SMEM);

    fp16 *W16, *PW16;
    cudaGetSymbolAddress((void**)&W16,  g_W16);
    cudaGetSymbolAddress((void**)&PW16, g_PW16);

    bias_kernel<<<HEADS * NTOK, 256>>>(table, rel_idx);
    cvt_x_kernel<<<NWIN * NTOK, 128>>>(x);
    cvt_w_kernel<<<(3 * DIMC * DIMC) / 1024, 256>>>(qkv_w, W16);
    cvt_w_kernel<<<(DIMC * DIMC) / 1024, 256>>>(proj_w, PW16);

    mgemm_kernel<0><<<dim3(256, 6), 256, MG_SMEM>>>(W16, qkv_b, nullptr);
    fattn_kernel<<<dim3(WH, 4), 256, FA_SMEM>>>(pe_w, pe_b);
    mgemm_kernel<1><<<dim3(256, 2), 256, MG_SMEM>>>(PW16, proj_b, out);
}